// round 4
// baseline (speedup 1.0000x reference)
#include <cuda_runtime.h>
#include <cuda_bf16.h>

typedef unsigned long long ull;

// ---------------- scratch (no allocation allowed) ----------------
__device__ float g_mods[16 * 5 * 512];   // [b][layer][gam|bet]
__device__ float g_loss[16];             // per-b summed loss
__device__ float g_q[16 * 256];          // z_q_sum per b

// ---------------- f32x2 helpers ----------------
__device__ __forceinline__ ull fma2(ull a, ull b, ull c) {
    ull d;
    asm("fma.rn.f32x2 %0, %1, %2, %3;" : "=l"(d) : "l"(a), "l"(b), "l"(c));
    return d;
}
__device__ __forceinline__ float2 unpk(ull v) {
    float lo, hi;
    asm("mov.b64 {%0, %1}, %2;" : "=f"(lo), "=f"(hi) : "l"(v));
    float2 r; r.x = lo; r.y = hi; return r;
}

// =================================================================
// Kernel 1: residual VQ. grid=16, 1024 thr (32 warps).
// Warp w scans codes [32w, 32w+32): coalesced row loads + butterfly
// dot. emb rows are unit-norm -> dist = 1 - 2*score.
// =================================================================
__global__ __launch_bounds__(1024)
void vq_kernel(const int* __restrict__ lidx,
               const float* __restrict__ latents,
               const float* __restrict__ emb) {
    __shared__ float r[256];
    __shared__ float q[256];
    __shared__ float wsc[32];
    __shared__ int   wci[32];
    __shared__ float s_d, s_r2;
    __shared__ int   s_c;

    const int b = blockIdx.x, t = threadIdx.x;
    const int lane = t & 31, wid = t >> 5;

    if (t < 256) {
        const float* lp = latents + (size_t)lidx[b] * 1024;
        float z = lp[t] + lp[256 + t] + lp[512 + t] + lp[768 + t];
        r[t] = z; q[t] = 0.f;
    }
    __syncthreads();

    // ||z||^2 (warp 0 from smem)
    if (wid == 0) {
        float rz = 0.f;
        #pragma unroll
        for (int j = 0; j < 8; ++j) { float v = r[lane * 8 + j]; rz = fmaf(v, v, rz); }
        #pragma unroll
        for (int o = 16; o; o >>= 1) rz += __shfl_xor_sync(~0u, rz, o);
        if (lane == 0) s_r2 = rz;
    }
    float loss = 0.f;   // thread 0 only
    __syncthreads();

    for (int s = 0; s < 4; ++s) {
        // lane-local r chunk
        float4 rj0 = reinterpret_cast<const float4*>(r)[lane * 2];
        float4 rj1 = reinterpret_cast<const float4*>(r)[lane * 2 + 1];

        float best = -3.4e38f;
        int   bi   = 0;
        const int c0 = wid * 32;
        #pragma unroll 4
        for (int i = 0; i < 32; ++i) {
            const int c = c0 + i;
            const float4* E4 = reinterpret_cast<const float4*>(emb)
                               + (size_t)(s * 1024 + c) * 64 + lane * 2;
            float4 e0 = E4[0], e1 = E4[1];
            float p = e0.x * rj0.x + e0.y * rj0.y + e0.z * rj0.z + e0.w * rj0.w
                    + e1.x * rj1.x + e1.y * rj1.y + e1.z * rj1.z + e1.w * rj1.w;
            #pragma unroll
            for (int o = 16; o; o >>= 1) p += __shfl_xor_sync(~0u, p, o);
            if (p > best) { best = p; bi = c; }   // ascending c => first-max kept
        }
        if (lane == 0) { wsc[wid] = best; wci[wid] = bi; }
        __syncthreads();
        if (wid == 0) {
            float v = wsc[lane]; int ci = wci[lane];
            #pragma unroll
            for (int o = 16; o; o >>= 1) {
                float ov = __shfl_down_sync(~0u, v,  o);
                int   oi = __shfl_down_sync(~0u, ci, o);
                if (ov > v || (ov == v && oi < ci)) { v = ov; ci = oi; }
            }
            if (lane == 0) { s_c = ci; s_d = 1.0f - 2.0f * v; }
        }
        __syncthreads();
        if (t == 0) { loss += s_d + s_r2; s_r2 += s_d; }
        const int cmin = s_c;
        if (t < 256) {
            float e = emb[((size_t)s * 1024 + cmin) * 256 + t];
            q[t] += e; r[t] -= e;
        }
        __syncthreads();
    }
    if (t == 0) g_loss[b] = loss;
    if (t < 256) g_q[b * 256 + t] = q[t];
}

// =================================================================
// Kernel 2: FiLM mods GEMM. grid (5 layers, 4 h-chunks), 128 thr.
// =================================================================
__global__ __launch_bounds__(128)
void mods_kernel(const float* __restrict__ mod_W,
                 const float* __restrict__ mod_b) {
    __shared__ float qt[256 * 16];   // [d][b]
    const int l = blockIdx.x, ch = blockIdx.y, t = threadIdx.x;
    for (int i = t; i < 4096; i += 128) {
        int bb = i >> 8, d = i & 255;
        qt[d * 16 + bb] = g_q[i];
    }
    __syncthreads();
    const int h = ch * 128 + t;
    float acc[16];
    const float bias = mod_b[l * 512 + h];
    #pragma unroll
    for (int bb = 0; bb < 16; bb++) acc[bb] = bias;
    const float* Wp = mod_W + (size_t)l * 131072 + h;
    #pragma unroll 4
    for (int d = 0; d < 256; ++d) {
        float w = Wp[(size_t)d * 512];
        const float4* q4 = reinterpret_cast<const float4*>(qt + d * 16);
        float4 a = q4[0], c = q4[1], e = q4[2], f = q4[3];
        acc[0]  = fmaf(a.x, w, acc[0]);  acc[1]  = fmaf(a.y, w, acc[1]);
        acc[2]  = fmaf(a.z, w, acc[2]);  acc[3]  = fmaf(a.w, w, acc[3]);
        acc[4]  = fmaf(c.x, w, acc[4]);  acc[5]  = fmaf(c.y, w, acc[5]);
        acc[6]  = fmaf(c.z, w, acc[6]);  acc[7]  = fmaf(c.w, w, acc[7]);
        acc[8]  = fmaf(e.x, w, acc[8]);  acc[9]  = fmaf(e.y, w, acc[9]);
        acc[10] = fmaf(e.z, w, acc[10]); acc[11] = fmaf(e.w, w, acc[11]);
        acc[12] = fmaf(f.x, w, acc[12]); acc[13] = fmaf(f.y, w, acc[13]);
        acc[14] = fmaf(f.z, w, acc[14]); acc[15] = fmaf(f.w, w, acc[15]);
    }
    #pragma unroll
    for (int bb = 0; bb < 16; bb++)
        g_mods[bb * 2560 + l * 512 + h] = acc[bb];
}

// =================================================================
// Kernel 3: finalize vq_loss -> d_out[out_size-1]  (sum / 65536)
// =================================================================
__global__ void loss_kernel(float* out, int out_size) {
    if (threadIdx.x == 0) {
        float s = 0.f;
        #pragma unroll
        for (int i = 0; i < 16; ++i) s += g_loss[i];
        out[out_size - 1] = s * (1.0f / 65536.0f);
    }
}

// =================================================================
// Kernel 4: fused SIREN decoder.
// grid (128 tiles, 16 b), 256 thr, M_TILE=32, 2 CTAs/SM.
// xsd: x stored DUPLICATED [m][2k] (row stride 516) so one LDS.128
// yields (xk,xk),(xk+1,xk+1) ulls -> zero MOVs. Weights LDS.128 ull2.
// Warp owns 4 m-rows exclusively -> no cross-warp xs hazards.
// Thread tile 4m x 8n; acc n-paired f32x2 (16 ull).
// =================================================================
#define RX 516

__global__ __launch_bounds__(256, 2)
void dec_kernel(const float* __restrict__ coords,
                const float* __restrict__ W0g,
                const float* __restrict__ b0g,
                const float* __restrict__ Whg,
                const float* __restrict__ bhg,
                const float* __restrict__ Wlg,
                const float* __restrict__ blg,
                float* __restrict__ out) {
    extern __shared__ float sm[];
    float* xsd  = sm;              // 32*516 = 16512
    float* wb   = xsd + 16512;     // 2 * 4096 = 8192
    float* film = wb + 8192;       // 2048
    float* w0s  = film + 2048;     // 768
    float* wls  = w0s + 768;       // 772
    float* cs   = wls + 772;       // 64

    const int b      = blockIdx.y;
    const int m_base = blockIdx.x * 32;
    const int t  = threadIdx.x;
    const int nt = t & 31;
    const int wd = t >> 5;         // 8 warps
    const int m0 = wd * 4;

    // ---- stage constants ----
    for (int i = t; i < 2048; i += 256) film[i] = g_mods[b * 2560 + 512 + i];
    for (int i = t; i < 768;  i += 256) w0s[i] = (i < 512) ? W0g[i] : b0g[i - 512];
    for (int i = t; i < 771;  i += 256) wls[i] = (i < 768) ? Wlg[i] : blg[i - 768];
    if (t < 64) cs[t] = coords[((size_t)(b * 4096 + m_base)) * 2 + t];
    __syncthreads();

    // prefetch weight panel 0 while layer-0 sins compute
    float4 pf[4];
    {
        const float4* Wg4 = reinterpret_cast<const float4*>(Whg);
        #pragma unroll
        for (int i = 0; i < 4; ++i) pf[i] = Wg4[t + i * 256];
    }

    // ---- layer 0 (each warp writes only its own 4 m-rows, dup) ----
    {
        const float2* cs2 = reinterpret_cast<const float2*>(cs);
        #pragma unroll
        for (int mi = 0; mi < 4; ++mi) {
            const int m = m0 + mi;
            const float2 c2 = cs2[m];
            float v[8];
            #pragma unroll
            for (int g = 0; g < 2; ++g)
                #pragma unroll
                for (int j = 0; j < 4; ++j) {
                    const int n = g * 128 + nt * 4 + j;
                    float pre = fmaf(c2.x, w0s[n], fmaf(c2.y, w0s[256 + n], w0s[512 + n]));
                    v[g * 4 + j] = __sinf(30.0f * pre);
                }
            float* row = xsd + m * RX;
            #pragma unroll
            for (int g = 0; g < 2; ++g) {
                float4 o1; o1.x = v[g*4+0]; o1.y = v[g*4+0]; o1.z = v[g*4+1]; o1.w = v[g*4+1];
                float4 o2; o2.x = v[g*4+2]; o2.y = v[g*4+2]; o2.z = v[g*4+3]; o2.w = v[g*4+3];
                *reinterpret_cast<float4*>(row + g * 256 + nt * 8)     = o1;
                *reinterpret_cast<float4*>(row + g * 256 + nt * 8 + 4) = o2;
            }
        }
    }

    ull acc[4][4];
    #pragma unroll
    for (int mi = 0; mi < 4; ++mi)
        #pragma unroll
        for (int j = 0; j < 4; ++j) acc[mi][j] = 0ull;

    // flattened 64-panel loop (4 layers x 16 panels of 16 k)
    for (int p = 0; p < 64; ++p) {
        float* buf = wb + (p & 1) * 4096;
        {   // commit prefetched panel
            float4* b4 = reinterpret_cast<float4*>(buf);
            #pragma unroll
            for (int i = 0; i < 4; ++i) b4[t + i * 256] = pf[i];
        }
        __syncthreads();

        if (p < 63) {
            const float4* Wg4 = reinterpret_cast<const float4*>(
                Whg + (size_t)((p + 1) >> 4) * 65536 + ((p + 1) & 15) * 4096);
            #pragma unroll
            for (int i = 0; i < 4; ++i) pf[i] = Wg4[t + i * 256];
        }

        const int kg0 = (p & 15) * 16;
        #pragma unroll
        for (int k2 = 0; k2 < 8; ++k2) {
            const int kk = 2 * k2;
            // weights: 4 ull2 (k row: groups 0,1; k+1 row: groups 0,1)
            const ulonglong2 wk0 = reinterpret_cast<const ulonglong2*>(buf + kk * 256)[nt];
            const ulonglong2 wk1 = reinterpret_cast<const ulonglong2*>(buf + kk * 256 + 128)[nt];
            const ulonglong2 wq0 = reinterpret_cast<const ulonglong2*>(buf + kk * 256 + 256)[nt];
            const ulonglong2 wq1 = reinterpret_cast<const ulonglong2*>(buf + kk * 256 + 384)[nt];
            #pragma unroll
            for (int mi = 0; mi < 4; ++mi) {
                // dup x pair: (xk,xk),(xk+1,xk+1) in one LDS.128 broadcast
                const ulonglong2 xv = *reinterpret_cast<const ulonglong2*>(
                    xsd + (m0 + mi) * RX + (kg0 + kk) * 2);
                acc[mi][0] = fma2(xv.x, wk0.x, fma2(xv.y, wq0.x, acc[mi][0]));
                acc[mi][1] = fma2(xv.x, wk0.y, fma2(xv.y, wq0.y, acc[mi][1]));
                acc[mi][2] = fma2(xv.x, wk1.x, fma2(xv.y, wq1.x, acc[mi][2]));
                acc[mi][3] = fma2(xv.x, wk1.y, fma2(xv.y, wq1.y, acc[mi][3]));
            }
        }

        if ((p & 15) == 15) {
            // epilogue: own rows only -> no barrier needed
            const int l = p >> 4;
            const float* fg  = film + l * 512;
            const float* fb  = fg + 256;
            const float* bhl = bhg + l * 256;
            float g1[8], be[8], bh[8];
            #pragma unroll
            for (int g = 0; g < 2; ++g)
                #pragma unroll
                for (int j = 0; j < 4; ++j) {
                    const int n = g * 128 + nt * 4 + j;
                    g1[g*4+j] = 1.0f + fg[n]; be[g*4+j] = fb[n]; bh[g*4+j] = bhl[n];
                }
            #pragma unroll
            for (int mi = 0; mi < 4; ++mi) {
                float* row = xsd + (m0 + mi) * RX;
                #pragma unroll
                for (int g = 0; g < 2; ++g) {
                    float2 ya = unpk(acc[mi][g * 2]);
                    float2 yb = unpk(acc[mi][g * 2 + 1]);
                    float v0 = __sinf(30.0f * fmaf(ya.x + bh[g*4+0], g1[g*4+0], be[g*4+0]));
                    float v1 = __sinf(30.0f * fmaf(ya.y + bh[g*4+1], g1[g*4+1], be[g*4+1]));
                    float v2 = __sinf(30.0f * fmaf(yb.x + bh[g*4+2], g1[g*4+2], be[g*4+2]));
                    float v3 = __sinf(30.0f * fmaf(yb.y + bh[g*4+3], g1[g*4+3], be[g*4+3]));
                    float4 o1; o1.x = v0; o1.y = v0; o1.z = v1; o1.w = v1;
                    float4 o2; o2.x = v2; o2.y = v2; o2.z = v3; o2.w = v3;
                    *reinterpret_cast<float4*>(row + g * 256 + nt * 8)     = o1;
                    *reinterpret_cast<float4*>(row + g * 256 + nt * 8 + 4) = o2;
                    acc[mi][g * 2] = 0ull; acc[mi][g * 2 + 1] = 0ull;
                }
            }
        }
    }
    __syncthreads();

    // ---- output head: values = x @ Wl + bl (read dup stride 2) ----
    if (t < 96) {
        const int m = t / 3, c = t - m * 3;
        float a0 = 0.f, a1 = 0.f, a2 = 0.f, a3 = 0.f;
        const float* xr = xsd + m * RX;
        #pragma unroll 8
        for (int k = 0; k < 256; k += 4) {
            a0 = fmaf(xr[2 * k],     wls[(k)     * 3 + c], a0);
            a1 = fmaf(xr[2 * k + 2], wls[(k + 1) * 3 + c], a1);
            a2 = fmaf(xr[2 * k + 4], wls[(k + 2) * 3 + c], a2);
            a3 = fmaf(xr[2 * k + 6], wls[(k + 3) * 3 + c], a3);
        }
        out[((size_t)(b * 4096 + m_base + m)) * 3 + c] =
            (a0 + a1) + (a2 + a3) + wls[768 + c];
    }
}

// =================================================================
extern "C" void kernel_launch(void* const* d_in, const int* in_sizes, int n_in,
                              void* d_out, int out_size) {
    const float* coords  = (const float*)d_in[0];
    const int*   lidx    = (const int*)  d_in[1];
    const float* latents = (const float*)d_in[2];
    const float* emb     = (const float*)d_in[3];
    const float* mod_W   = (const float*)d_in[4];
    const float* mod_b   = (const float*)d_in[5];
    const float* W0      = (const float*)d_in[6];
    const float* b0      = (const float*)d_in[7];
    const float* Wh      = (const float*)d_in[8];
    const float* bh      = (const float*)d_in[9];
    const float* Wl      = (const float*)d_in[10];
    const float* bl      = (const float*)d_in[11];
    float* out = (float*)d_out;

    vq_kernel<<<16, 1024>>>(lidx, latents, emb);
    mods_kernel<<<dim3(5, 4), 128>>>(mod_W, mod_b);
    loss_kernel<<<1, 32>>>(out, out_size);

    const size_t smem = (16512 + 8192 + 2048 + 768 + 772 + 64) * sizeof(float); // 113424 B
    cudaFuncSetAttribute(dec_kernel, cudaFuncAttributeMaxDynamicSharedMemorySize, (int)smem);
    dec_kernel<<<dim3(128, 16), 256, smem>>>(coords, W0, b0, Wh, bh, Wl, bl, out);
}

// round 5
// speedup vs baseline: 1.1486x; 1.1486x over previous
#include <cuda_runtime.h>
#include <cuda_bf16.h>

typedef unsigned long long ull;

// ---------------- scratch (no allocation allowed) ----------------
__device__ float g_mods[16 * 5 * 512];   // [b][layer][gam|bet]
__device__ float g_loss[16];             // per-b summed loss
__device__ float g_q[16 * 256];          // z_q_sum per b

// ---------------- helpers ----------------
__device__ __forceinline__ ull fma2(ull a, ull b, ull c) {
    ull d;
    asm("fma.rn.f32x2 %0, %1, %2, %3;" : "=l"(d) : "l"(a), "l"(b), "l"(c));
    return d;
}
__device__ __forceinline__ float2 unpk(ull v) {
    float lo, hi;
    asm("mov.b64 {%0, %1}, %2;" : "=f"(lo), "=f"(hi) : "l"(v));
    float2 r; r.x = lo; r.y = hi; return r;
}
__device__ __forceinline__ void cp16(float* dst, const float* src) {
    unsigned s = (unsigned)__cvta_generic_to_shared(dst);
    asm volatile("cp.async.ca.shared.global [%0], [%1], 16;" :: "r"(s), "l"(src));
}

// =================================================================
// Kernel 1: residual VQ. grid=16, 1024 thr (32 warps).
// Warp w scans codes [32w,32w+32): coalesced rows + butterfly dot.
// emb rows unit-norm -> dist = 1 - 2*score.
// =================================================================
__global__ __launch_bounds__(1024)
void vq_kernel(const int* __restrict__ lidx,
               const float* __restrict__ latents,
               const float* __restrict__ emb) {
    __shared__ float r[256];
    __shared__ float q[256];
    __shared__ float wsc[32];
    __shared__ int   wci[32];
    __shared__ float s_d, s_r2;
    __shared__ int   s_c;

    const int b = blockIdx.x, t = threadIdx.x;
    const int lane = t & 31, wid = t >> 5;

    if (t < 256) {
        const float* lp = latents + (size_t)lidx[b] * 1024;
        float z = lp[t] + lp[256 + t] + lp[512 + t] + lp[768 + t];
        r[t] = z; q[t] = 0.f;
    }
    __syncthreads();

    if (wid == 0) {
        float rz = 0.f;
        #pragma unroll
        for (int j = 0; j < 8; ++j) { float v = r[lane * 8 + j]; rz = fmaf(v, v, rz); }
        #pragma unroll
        for (int o = 16; o; o >>= 1) rz += __shfl_xor_sync(~0u, rz, o);
        if (lane == 0) s_r2 = rz;
    }
    float loss = 0.f;
    __syncthreads();

    for (int s = 0; s < 4; ++s) {
        float4 rj0 = reinterpret_cast<const float4*>(r)[lane * 2];
        float4 rj1 = reinterpret_cast<const float4*>(r)[lane * 2 + 1];

        float best = -3.4e38f;
        int   bi   = 0;
        const int c0 = wid * 32;
        #pragma unroll 4
        for (int i = 0; i < 32; ++i) {
            const int c = c0 + i;
            const float4* E4 = reinterpret_cast<const float4*>(emb)
                               + (size_t)(s * 1024 + c) * 64 + lane * 2;
            float4 e0 = E4[0], e1 = E4[1];
            float p = e0.x * rj0.x + e0.y * rj0.y + e0.z * rj0.z + e0.w * rj0.w
                    + e1.x * rj1.x + e1.y * rj1.y + e1.z * rj1.z + e1.w * rj1.w;
            #pragma unroll
            for (int o = 16; o; o >>= 1) p += __shfl_xor_sync(~0u, p, o);
            if (p > best) { best = p; bi = c; }
        }
        if (lane == 0) { wsc[wid] = best; wci[wid] = bi; }
        __syncthreads();
        if (wid == 0) {
            float v = wsc[lane]; int ci = wci[lane];
            #pragma unroll
            for (int o = 16; o; o >>= 1) {
                float ov = __shfl_down_sync(~0u, v,  o);
                int   oi = __shfl_down_sync(~0u, ci, o);
                if (ov > v || (ov == v && oi < ci)) { v = ov; ci = oi; }
            }
            if (lane == 0) { s_c = ci; s_d = 1.0f - 2.0f * v; }
        }
        __syncthreads();
        if (t == 0) { loss += s_d + s_r2; s_r2 += s_d; }
        const int cmin = s_c;
        if (t < 256) {
            float e = emb[((size_t)s * 1024 + cmin) * 256 + t];
            q[t] += e; r[t] -= e;
        }
        __syncthreads();
    }
    if (t == 0) g_loss[b] = loss;
    if (t < 256) g_q[b * 256 + t] = q[t];
}

// =================================================================
// Kernel 2: FiLM mods GEMM. grid (5 layers, 4 h-chunks), 128 thr.
// =================================================================
__global__ __launch_bounds__(128)
void mods_kernel(const float* __restrict__ mod_W,
                 const float* __restrict__ mod_b) {
    __shared__ float qt[256 * 16];   // [d][b]
    const int l = blockIdx.x, ch = blockIdx.y, t = threadIdx.x;
    for (int i = t; i < 4096; i += 128) {
        int bb = i >> 8, d = i & 255;
        qt[d * 16 + bb] = g_q[i];
    }
    __syncthreads();
    const int h = ch * 128 + t;
    float acc[16];
    const float bias = mod_b[l * 512 + h];
    #pragma unroll
    for (int bb = 0; bb < 16; bb++) acc[bb] = bias;
    const float* Wp = mod_W + (size_t)l * 131072 + h;
    #pragma unroll 4
    for (int d = 0; d < 256; ++d) {
        float w = Wp[(size_t)d * 512];
        const float4* q4 = reinterpret_cast<const float4*>(qt + d * 16);
        float4 a = q4[0], c = q4[1], e = q4[2], f = q4[3];
        acc[0]  = fmaf(a.x, w, acc[0]);  acc[1]  = fmaf(a.y, w, acc[1]);
        acc[2]  = fmaf(a.z, w, acc[2]);  acc[3]  = fmaf(a.w, w, acc[3]);
        acc[4]  = fmaf(c.x, w, acc[4]);  acc[5]  = fmaf(c.y, w, acc[5]);
        acc[6]  = fmaf(c.z, w, acc[6]);  acc[7]  = fmaf(c.w, w, acc[7]);
        acc[8]  = fmaf(e.x, w, acc[8]);  acc[9]  = fmaf(e.y, w, acc[9]);
        acc[10] = fmaf(e.z, w, acc[10]); acc[11] = fmaf(e.w, w, acc[11]);
        acc[12] = fmaf(f.x, w, acc[12]); acc[13] = fmaf(f.y, w, acc[13]);
        acc[14] = fmaf(f.z, w, acc[14]); acc[15] = fmaf(f.w, w, acc[15]);
    }
    #pragma unroll
    for (int bb = 0; bb < 16; bb++)
        g_mods[bb * 2560 + l * 512 + h] = acc[bb];
}

// =================================================================
// Kernel 3: finalize vq_loss -> d_out[out_size-1]  (sum / 65536)
// =================================================================
__global__ void loss_kernel(float* out, int out_size) {
    if (threadIdx.x == 0) {
        float s = 0.f;
        #pragma unroll
        for (int i = 0; i < 16; ++i) s += g_loss[i];
        out[out_size - 1] = s * (1.0f / 65536.0f);
    }
}

// =================================================================
// Kernel 4: fused SIREN decoder.
// grid (64 tiles, 16 b), 256 thr, M_TILE=64, 2 CTAs/SM.
// 8 warps each own 8 m-rows. Thread tile 8m x 8n (n-paired f32x2).
// Per 16-k panel: warp copies its rows' k-slice into small dup
// buffer xd (warp-local, __syncwarp only). Inner: x via LDS.128
// broadcast of dup pairs (zero MOVs), weights via LDS.128 ull2.
// Panels fetched with cp.async, double-buffered.
// =================================================================
#define RXD 36

__global__ __launch_bounds__(256, 2)
void dec_kernel(const float* __restrict__ coords,
                const float* __restrict__ W0g,
                const float* __restrict__ b0g,
                const float* __restrict__ Whg,
                const float* __restrict__ bhg,
                const float* __restrict__ Wlg,
                const float* __restrict__ blg,
                float* __restrict__ out) {
    extern __shared__ float sm[];
    float* xs  = sm;             // 64*256 = 16384
    float* wb  = xs + 16384;     // 2*4096 = 8192
    float* xd  = wb + 8192;      // 64*36 = 2304
    float* w0s = xd + 2304;      // 768
    float* cs  = w0s + 768;      // 128

    const int b      = blockIdx.y;
    const int m_base = blockIdx.x * 64;
    const int t  = threadIdx.x;
    const int nt = t & 31;
    const int wd = t >> 5;       // 8 warps
    const int m0 = wd * 8;

    for (int i = t; i < 768; i += 256) w0s[i] = (i < 512) ? W0g[i] : b0g[i - 512];
    if (t < 128) cs[t] = coords[((size_t)(b * 4096 + m_base)) * 2 + t];

    // prefetch weight panel 0 via cp.async (overlaps layer-0 compute)
    {
        const float* src = Whg + t * 4;
        float* dst = wb + t * 4;
        #pragma unroll
        for (int i = 0; i < 4; ++i) cp16(dst + i * 1024, src + i * 1024);
        asm volatile("cp.async.commit_group;");
    }
    __syncthreads();

    // ---- layer 0: each warp writes its own 8 rows ----
    {
        const float2* cs2 = reinterpret_cast<const float2*>(cs);
        #pragma unroll
        for (int mi = 0; mi < 8; ++mi) {
            const int m = m0 + mi;
            const float2 c2 = cs2[m];
            #pragma unroll
            for (int g = 0; g < 2; ++g) {
                float4 o;
                #pragma unroll
                for (int j = 0; j < 4; ++j) {
                    const int n = g * 128 + nt * 4 + j;
                    float pre = fmaf(c2.x, w0s[n], fmaf(c2.y, w0s[256 + n], w0s[512 + n]));
                    ((float*)&o)[j] = __sinf(30.0f * pre);
                }
                *reinterpret_cast<float4*>(xs + m * 256 + g * 128 + nt * 4) = o;
            }
        }
    }

    ull acc[8][4];
    #pragma unroll
    for (int mi = 0; mi < 8; ++mi)
        #pragma unroll
        for (int j = 0; j < 4; ++j) acc[mi][j] = 0ull;

    for (int p = 0; p < 64; ++p) {
        asm volatile("cp.async.wait_group 0;");
        __syncthreads();           // panel p present; all done with p-1

        if (p < 63) {
            const float* src = Whg + (size_t)((p + 1) >> 4) * 65536
                                   + ((p + 1) & 15) * 4096 + t * 4;
            float* dst = wb + ((p + 1) & 1) * 4096 + t * 4;
            #pragma unroll
            for (int i = 0; i < 4; ++i) cp16(dst + i * 1024, src + i * 1024);
            asm volatile("cp.async.commit_group;");
        }

        const int kg0 = (p & 15) * 16;

        // warp-local dup copy of own rows' 16-k slice
        {
            const int r  = m0 + (nt >> 2);
            const int qd = nt & 3;
            float4 v = *reinterpret_cast<const float4*>(xs + r * 256 + kg0 + qd * 4);
            float4 o1; o1.x = v.x; o1.y = v.x; o1.z = v.y; o1.w = v.y;
            float4 o2; o2.x = v.z; o2.y = v.z; o2.z = v.w; o2.w = v.w;
            *reinterpret_cast<float4*>(xd + r * RXD + qd * 8)     = o1;
            *reinterpret_cast<float4*>(xd + r * RXD + qd * 8 + 4) = o2;
        }
        __syncwarp();

        const float* buf = wb + (p & 1) * 4096;
        #pragma unroll
        for (int k2 = 0; k2 < 8; ++k2) {
            const int kk = 2 * k2;
            const ulonglong2 wk0 = reinterpret_cast<const ulonglong2*>(buf + kk * 256)[nt];
            const ulonglong2 wk1 = reinterpret_cast<const ulonglong2*>(buf + kk * 256 + 128)[nt];
            const ulonglong2 wq0 = reinterpret_cast<const ulonglong2*>(buf + kk * 256 + 256)[nt];
            const ulonglong2 wq1 = reinterpret_cast<const ulonglong2*>(buf + kk * 256 + 384)[nt];
            #pragma unroll
            for (int mi = 0; mi < 8; ++mi) {
                const ulonglong2 xv = *reinterpret_cast<const ulonglong2*>(
                    xd + (m0 + mi) * RXD + kk * 2);
                acc[mi][0] = fma2(xv.x, wk0.x, fma2(xv.y, wq0.x, acc[mi][0]));
                acc[mi][1] = fma2(xv.x, wk0.y, fma2(xv.y, wq0.y, acc[mi][1]));
                acc[mi][2] = fma2(xv.x, wk1.x, fma2(xv.y, wq1.x, acc[mi][2]));
                acc[mi][3] = fma2(xv.x, wk1.y, fma2(xv.y, wq1.y, acc[mi][3]));
            }
        }

        if ((p & 15) == 15) {
            const int l = p >> 4;
            const float* fg  = g_mods + b * 2560 + 512 + l * 512;
            const float* fb  = fg + 256;
            const float* bhl = bhg + l * 256;
            float g1[8], be[8], bh[8];
            #pragma unroll
            for (int g = 0; g < 2; ++g)
                #pragma unroll
                for (int j = 0; j < 4; ++j) {
                    const int n = g * 128 + nt * 4 + j;
                    g1[g*4+j] = 1.0f + fg[n]; be[g*4+j] = fb[n]; bh[g*4+j] = bhl[n];
                }
            #pragma unroll
            for (int mi = 0; mi < 8; ++mi) {
                #pragma unroll
                for (int g = 0; g < 2; ++g) {
                    float2 ya = unpk(acc[mi][g * 2]);
                    float2 yb = unpk(acc[mi][g * 2 + 1]);
                    float4 o;
                    o.x = __sinf(30.0f * fmaf(ya.x + bh[g*4+0], g1[g*4+0], be[g*4+0]));
                    o.y = __sinf(30.0f * fmaf(ya.y + bh[g*4+1], g1[g*4+1], be[g*4+1]));
                    o.z = __sinf(30.0f * fmaf(yb.x + bh[g*4+2], g1[g*4+2], be[g*4+2]));
                    o.w = __sinf(30.0f * fmaf(yb.y + bh[g*4+3], g1[g*4+3], be[g*4+3]));
                    *reinterpret_cast<float4*>(xs + (m0 + mi) * 256 + g * 128 + nt * 4) = o;
                    acc[mi][g * 2] = 0ull; acc[mi][g * 2 + 1] = 0ull;
                }
            }
        }
    }
    __syncthreads();

    // ---- output head: values = x @ Wl + bl ----
    if (t < 192) {
        const int m = t / 3, c = t - m * 3;
        float a0 = 0.f, a1 = 0.f, a2 = 0.f, a3 = 0.f;
        const float* xr = xs + m * 256;
        #pragma unroll 8
        for (int k = 0; k < 256; k += 4) {
            a0 = fmaf(xr[k],     Wlg[(k)     * 3 + c], a0);
            a1 = fmaf(xr[k + 1], Wlg[(k + 1) * 3 + c], a1);
            a2 = fmaf(xr[k + 2], Wlg[(k + 2) * 3 + c], a2);
            a3 = fmaf(xr[k + 3], Wlg[(k + 3) * 3 + c], a3);
        }
        out[((size_t)(b * 4096 + m_base + m)) * 3 + c] =
            (a0 + a1) + (a2 + a3) + blg[c];
    }
}

// =================================================================
extern "C" void kernel_launch(void* const* d_in, const int* in_sizes, int n_in,
                              void* d_out, int out_size) {
    const float* coords  = (const float*)d_in[0];
    const int*   lidx    = (const int*)  d_in[1];
    const float* latents = (const float*)d_in[2];
    const float* emb     = (const float*)d_in[3];
    const float* mod_W   = (const float*)d_in[4];
    const float* mod_b   = (const float*)d_in[5];
    const float* W0      = (const float*)d_in[6];
    const float* b0      = (const float*)d_in[7];
    const float* Wh      = (const float*)d_in[8];
    const float* bh      = (const float*)d_in[9];
    const float* Wl      = (const float*)d_in[10];
    const float* bl      = (const float*)d_in[11];
    float* out = (float*)d_out;

    vq_kernel<<<16, 1024>>>(lidx, latents, emb);
    mods_kernel<<<dim3(5, 4), 128>>>(mod_W, mod_b);
    loss_kernel<<<1, 32>>>(out, out_size);

    const size_t smem = (16384 + 8192 + 2304 + 768 + 128) * sizeof(float); // 111104 B
    cudaFuncSetAttribute(dec_kernel, cudaFuncAttributeMaxDynamicSharedMemorySize, (int)smem);
    dec_kernel<<<dim3(64, 16), 256, smem>>>(coords, W0, b0, Wh, bh, Wl, bl, out);
}

// round 8
// speedup vs baseline: 1.5972x; 1.3905x over previous
#include <cuda_runtime.h>
#include <cuda_bf16.h>
#include <cstdint>

typedef unsigned long long ull;

// ---------------- scratch (no allocation allowed) ----------------
__device__ float g_mods[16 * 5 * 512];         // [b][layer][gam|bet]
__device__ float g_loss[16];                   // per-b summed loss
__device__ float g_q[16 * 256];                // z_q_sum per b
// transposed + bf16 hi/lo split weights:
// [layer][plane hi/lo][n=256][k=256] bf16  -> 4 * 2 * 131072 bytes
__device__ unsigned char g_B[4 * 2 * 131072];

// ---------------- helpers ----------------
__device__ __forceinline__ uint32_t smem_u32(const void* p) {
    uint32_t a;
    asm("{ .reg .u64 t; cvta.to.shared.u64 t, %1; cvt.u32.u64 %0, t; }"
        : "=r"(a) : "l"(p));
    return a;
}
__device__ __forceinline__ void cp16(void* dst, const void* src) {
    unsigned s = smem_u32(dst);
    asm volatile("cp.async.ca.shared.global [%0], [%1], 16;" :: "r"(s), "l"(src));
}
__device__ __forceinline__ void ldm_x4(uint32_t* r, const void* p) {
    uint32_t a = smem_u32(p);
    asm volatile("ldmatrix.sync.aligned.m8n8.x4.shared.b16 {%0,%1,%2,%3}, [%4];"
                 : "=r"(r[0]), "=r"(r[1]), "=r"(r[2]), "=r"(r[3]) : "r"(a));
}
__device__ __forceinline__ void ldm_x2(uint32_t* r, const void* p) {
    uint32_t a = smem_u32(p);
    asm volatile("ldmatrix.sync.aligned.m8n8.x2.shared.b16 {%0,%1}, [%2];"
                 : "=r"(r[0]), "=r"(r[1]) : "r"(a));
}
__device__ __forceinline__ void mma16816(float* c, const uint32_t* a, const uint32_t* b) {
    asm volatile(
        "mma.sync.aligned.m16n8k16.row.col.f32.bf16.bf16.f32 "
        "{%0,%1,%2,%3}, {%4,%5,%6,%7}, {%8,%9}, {%0,%1,%2,%3};"
        : "+f"(c[0]), "+f"(c[1]), "+f"(c[2]), "+f"(c[3])
        : "r"(a[0]), "r"(a[1]), "r"(a[2]), "r"(a[3]), "r"(b[0]), "r"(b[1]));
}
__device__ __forceinline__ uint32_t pack_split(float x0, float x1, uint32_t& lo_out) {
    __nv_bfloat16 h0 = __float2bfloat16(x0);
    __nv_bfloat16 h1 = __float2bfloat16(x1);
    __nv_bfloat16 l0 = __float2bfloat16(x0 - __bfloat162float(h0));
    __nv_bfloat16 l1 = __float2bfloat16(x1 - __bfloat162float(h1));
    lo_out = ((uint32_t)__bfloat16_as_ushort(l1) << 16) | __bfloat16_as_ushort(l0);
    return ((uint32_t)__bfloat16_as_ushort(h1) << 16) | __bfloat16_as_ushort(h0);
}

// =================================================================
// Kernel 1: residual VQ (R5, passing)
// =================================================================
__global__ __launch_bounds__(1024)
void vq_kernel(const int* __restrict__ lidx,
               const float* __restrict__ latents,
               const float* __restrict__ emb) {
    __shared__ float r[256];
    __shared__ float q[256];
    __shared__ float wsc[32];
    __shared__ int   wci[32];
    __shared__ float s_d, s_r2;
    __shared__ int   s_c;

    const int b = blockIdx.x, t = threadIdx.x;
    const int lane = t & 31, wid = t >> 5;

    if (t < 256) {
        const float* lp = latents + (size_t)lidx[b] * 1024;
        float z = lp[t] + lp[256 + t] + lp[512 + t] + lp[768 + t];
        r[t] = z; q[t] = 0.f;
    }
    __syncthreads();

    if (wid == 0) {
        float rz = 0.f;
        #pragma unroll
        for (int j = 0; j < 8; ++j) { float v = r[lane * 8 + j]; rz = fmaf(v, v, rz); }
        #pragma unroll
        for (int o = 16; o; o >>= 1) rz += __shfl_xor_sync(~0u, rz, o);
        if (lane == 0) s_r2 = rz;
    }
    float loss = 0.f;
    __syncthreads();

    for (int s = 0; s < 4; ++s) {
        float4 rj0 = reinterpret_cast<const float4*>(r)[lane * 2];
        float4 rj1 = reinterpret_cast<const float4*>(r)[lane * 2 + 1];
        float best = -3.4e38f;
        int   bi   = 0;
        const int c0 = wid * 32;
        #pragma unroll 4
        for (int i = 0; i < 32; ++i) {
            const int c = c0 + i;
            const float4* E4 = reinterpret_cast<const float4*>(emb)
                               + (size_t)(s * 1024 + c) * 64 + lane * 2;
            float4 e0 = E4[0], e1 = E4[1];
            float p = e0.x * rj0.x + e0.y * rj0.y + e0.z * rj0.z + e0.w * rj0.w
                    + e1.x * rj1.x + e1.y * rj1.y + e1.z * rj1.z + e1.w * rj1.w;
            #pragma unroll
            for (int o = 16; o; o >>= 1) p += __shfl_xor_sync(~0u, p, o);
            if (p > best) { best = p; bi = c; }
        }
        if (lane == 0) { wsc[wid] = best; wci[wid] = bi; }
        __syncthreads();
        if (wid == 0) {
            float v = wsc[lane]; int ci = wci[lane];
            #pragma unroll
            for (int o = 16; o; o >>= 1) {
                float ov = __shfl_down_sync(~0u, v,  o);
                int   oi = __shfl_down_sync(~0u, ci, o);
                if (ov > v || (ov == v && oi < ci)) { v = ov; ci = oi; }
            }
            if (lane == 0) { s_c = ci; s_d = 1.0f - 2.0f * v; }
        }
        __syncthreads();
        if (t == 0) { loss += s_d + s_r2; s_r2 += s_d; }
        const int cmin = s_c;
        if (t < 256) {
            float e = emb[((size_t)s * 1024 + cmin) * 256 + t];
            q[t] += e; r[t] -= e;
        }
        __syncthreads();
    }
    if (t == 0) g_loss[b] = loss;
    if (t < 256) g_q[b * 256 + t] = q[t];
}

// =================================================================
// Kernel 2: FiLM mods GEMM (R5, passing)
// =================================================================
__global__ __launch_bounds__(128)
void mods_kernel(const float* __restrict__ mod_W,
                 const float* __restrict__ mod_b) {
    __shared__ float qt[256 * 16];
    const int l = blockIdx.x, ch = blockIdx.y, t = threadIdx.x;
    for (int i = t; i < 4096; i += 128) {
        int bb = i >> 8, d = i & 255;
        qt[d * 16 + bb] = g_q[i];
    }
    __syncthreads();
    const int h = ch * 128 + t;
    float acc[16];
    const float bias = mod_b[l * 512 + h];
    #pragma unroll
    for (int bb = 0; bb < 16; bb++) acc[bb] = bias;
    const float* Wp = mod_W + (size_t)l * 131072 + h;
    #pragma unroll 4
    for (int d = 0; d < 256; ++d) {
        float w = Wp[(size_t)d * 512];
        const float4* q4 = reinterpret_cast<const float4*>(qt + d * 16);
        float4 a = q4[0], c = q4[1], e = q4[2], f = q4[3];
        acc[0]  = fmaf(a.x, w, acc[0]);  acc[1]  = fmaf(a.y, w, acc[1]);
        acc[2]  = fmaf(a.z, w, acc[2]);  acc[3]  = fmaf(a.w, w, acc[3]);
        acc[4]  = fmaf(c.x, w, acc[4]);  acc[5]  = fmaf(c.y, w, acc[5]);
        acc[6]  = fmaf(c.z, w, acc[6]);  acc[7]  = fmaf(c.w, w, acc[7]);
        acc[8]  = fmaf(e.x, w, acc[8]);  acc[9]  = fmaf(e.y, w, acc[9]);
        acc[10] = fmaf(e.z, w, acc[10]); acc[11] = fmaf(e.w, w, acc[11]);
        acc[12] = fmaf(f.x, w, acc[12]); acc[13] = fmaf(f.y, w, acc[13]);
        acc[14] = fmaf(f.z, w, acc[14]); acc[15] = fmaf(f.w, w, acc[15]);
    }
    #pragma unroll
    for (int bb = 0; bb < 16; bb++)
        g_mods[bb * 2560 + l * 512 + h] = acc[bb];
}

// =================================================================
// Kernel 3: vq_loss finalize
// =================================================================
__global__ void loss_kernel(float* out, int out_size) {
    if (threadIdx.x == 0) {
        float s = 0.f;
        #pragma unroll
        for (int i = 0; i < 16; ++i) s += g_loss[i];
        out[out_size - 1] = s * (1.0f / 65536.0f);
    }
}

// =================================================================
// Kernel 4: weight prep — Wt[n][k] bf16 hi/lo planes (131072 B each).
// grid 512 x 256; coalesced LDG over n.
// =================================================================
__global__ __launch_bounds__(256)
void prep_kernel(const float* __restrict__ Whg) {
    const int i = blockIdx.x * 256 + threadIdx.x;   // 131072 total
    const int layer = i >> 15;
    const int kp    = (i >> 8) & 127;
    const int n     = i & 255;
    const int k     = kp * 2;
    float w0 = Whg[(size_t)layer * 65536 + (size_t)k * 256 + n];
    float w1 = Whg[(size_t)layer * 65536 + (size_t)(k + 1) * 256 + n];
    uint32_t lo, hi = pack_split(w0, w1, lo);
    unsigned char* base = g_B + (size_t)layer * 262144;
    *reinterpret_cast<uint32_t*>(base + n * 512 + k * 2)          = hi;
    *reinterpret_cast<uint32_t*>(base + 131072 + n * 512 + k * 2) = lo;
}

// =================================================================
// Kernel 5: HMMA SIREN decoder.
// grid (32 tiles, 16 b), 256 thr, M_TILE=128, 1 CTA/SM.
// A planes: [128m][256k] bf16 hi/lo, pitch 528B.
// B: 32-k chunks [256n][32k] hi/lo, pitch 80B, double-buffered cp.async.
// Warp tile 32m x 128n; 3-term product Ah*Bh + Al*Bh + Ah*Bl.
// =================================================================
#define A_PITCH 528
#define A_PLANE 67584
#define B_ROW   80
#define B_PLANE 20480
#define B_BUF   40960

__global__ __launch_bounds__(256, 1)
void dec_mma(const float* __restrict__ coords,
             const float* __restrict__ W0g,
             const float* __restrict__ b0g,
             const float* __restrict__ bhg,
             const float* __restrict__ Wlg,
             const float* __restrict__ blg,
             float* __restrict__ out) {
    extern __shared__ char smc[];
    char*  Ah   = smc;                         // 67584
    char*  Al   = smc + A_PLANE;               // 67584
    char*  Bb   = smc + 2 * A_PLANE;           // 81920 (2 bufs x 2 planes)
    float* w0s  = (float*)(smc + 217088);      // 768 f
    float* film = (float*)(smc + 220160);      // 768 f (gam|bet|bh, one layer)
    float* red  = (float*)(smc + 223232);      // 128*6 f
    // total 226304 B

    const int b      = blockIdx.y;
    const int m_base = blockIdx.x * 128;
    const int t  = threadIdx.x;
    const int L  = t & 31;
    const int wid = t >> 5;
    const int wm = wid >> 1;       // 0..3 (m)
    const int wn = wid & 1;        // 0..1 (n)

    // stage W0/b0
    for (int i = t; i < 768; i += 256) w0s[i] = (i < 512) ? W0g[i] : b0g[i - 512];

    // prefetch B chunk 0 (layer 0, kc 0) into buf 0
    {
        const unsigned char* s0 = g_B + t * 512;          // row n=t, k0
        char* d0 = Bb + t * B_ROW;
        #pragma unroll
        for (int j = 0; j < 4; ++j) cp16(d0 + j * 16, s0 + j * 16);
        const unsigned char* s1 = s0 + 131072;
        char* d1 = d0 + B_PLANE;
        #pragma unroll
        for (int j = 0; j < 4; ++j) cp16(d1 + j * 16, s1 + j * 16);
        asm volatile("cp.async.commit_group;");
    }
    __syncthreads();

    // ---- layer 0: fill A planes ----
    {
        const int m = t >> 1, half = t & 1;
        const float2 c2 = reinterpret_cast<const float2*>(coords)[b * 4096 + m_base + m];
        char* rowH = Ah + m * A_PITCH;
        char* rowL = Al + m * A_PITCH;
        #pragma unroll 4
        for (int n = half * 128; n < half * 128 + 128; n += 2) {
            float p0 = fmaf(c2.x, w0s[n],     fmaf(c2.y, w0s[256 + n],     w0s[512 + n]));
            float p1 = fmaf(c2.x, w0s[n + 1], fmaf(c2.y, w0s[256 + n + 1], w0s[512 + n + 1]));
            float x0 = __sinf(30.0f * p0);
            float x1 = __sinf(30.0f * p1);
            uint32_t lo, hi = pack_split(x0, x1, lo);
            *reinterpret_cast<uint32_t*>(rowH + n * 2) = hi;
            *reinterpret_cast<uint32_t*>(rowL + n * 2) = lo;
        }
    }

    float acc[2][16][4];
    #pragma unroll
    for (int mt = 0; mt < 2; ++mt)
        #pragma unroll
        for (int nt = 0; nt < 16; ++nt)
            #pragma unroll
            for (int j = 0; j < 4; ++j) acc[mt][nt][j] = 0.f;

    // 32 iterations: 4 layers x 8 chunks of 32 k
    for (int p = 0; p < 32; ++p) {
        __syncthreads();   // prev compute done; epilogue A writes visible

        if (p < 31) {      // prefetch chunk p+1
            const int pl = (p + 1) >> 3, pk = (p + 1) & 7;
            const unsigned char* s0 = g_B + (size_t)pl * 262144 + t * 512 + pk * 64;
            char* d0 = Bb + ((p + 1) & 1) * B_BUF + t * B_ROW;
            #pragma unroll
            for (int j = 0; j < 4; ++j) cp16(d0 + j * 16, s0 + j * 16);
            const unsigned char* s1 = s0 + 131072;
            char* d1 = d0 + B_PLANE;
            #pragma unroll
            for (int j = 0; j < 4; ++j) cp16(d1 + j * 16, s1 + j * 16);
            asm volatile("cp.async.commit_group;");
            asm volatile("cp.async.wait_group 1;");
        } else {
            asm volatile("cp.async.wait_group 0;");
        }
        __syncthreads();   // chunk p visible

        const int l   = p >> 3;
        const int k0g = (p & 7) * 32;

        if ((p & 7) == 7) {   // preload film for this layer (read after next sync)
            for (int i = t; i < 768; i += 256)
                film[i] = (i < 512) ? g_mods[b * 2560 + 512 + l * 512 + i]
                                    : bhg[l * 256 + (i - 512)];
        }

        const char* Bbuf = Bb + (p & 1) * B_BUF;
        #pragma unroll
        for (int kt = 0; kt < 2; ++kt) {
            uint32_t ah[2][4], al[2][4];
            const int acol = (k0g + kt * 16 + (L >> 4) * 8) * 2;
            #pragma unroll
            for (int mt = 0; mt < 2; ++mt) {
                const int arow = 32 * wm + 16 * mt + (L & 15);
                ldm_x4(ah[mt], Ah + arow * A_PITCH + acol);
                ldm_x4(al[mt], Al + arow * A_PITCH + acol);
            }
            #pragma unroll
            for (int nt = 0; nt < 16; ++nt) {
                uint32_t bh2[2], bl2[2];
                const unsigned boff = (unsigned)(128 * wn + 8 * nt + (L & 7)) * B_ROW
                                    + (unsigned)(kt * 16 + ((L >> 3) & 1) * 8) * 2;
                ldm_x2(bh2, Bbuf + boff);
                ldm_x2(bl2, Bbuf + B_PLANE + boff);
                #pragma unroll
                for (int mt = 0; mt < 2; ++mt) {
                    mma16816(acc[mt][nt], ah[mt], bh2);
                    mma16816(acc[mt][nt], al[mt], bh2);
                    mma16816(acc[mt][nt], ah[mt], bl2);
                }
            }
        }

        if ((p & 7) == 7) {
            __syncthreads();   // all compute done; film visible
            if (l < 3) {
                // FiLM + sin -> A planes; zero acc
                #pragma unroll
                for (int mt = 0; mt < 2; ++mt) {
                    const int r0 = 32 * wm + 16 * mt + (L >> 2);
                    #pragma unroll
                    for (int nt = 0; nt < 16; ++nt) {
                        const int n0 = 128 * wn + 8 * nt + 2 * (L & 3);
                        const float g0 = 1.0f + film[n0], g1 = 1.0f + film[n0 + 1];
                        const float e0 = film[256 + n0],  e1 = film[256 + n0 + 1];
                        const float h0 = film[512 + n0],  h1 = film[512 + n0 + 1];
                        float* a = acc[mt][nt];
                        float x00 = __sinf(30.0f * fmaf(a[0] + h0, g0, e0));
                        float x01 = __sinf(30.0f * fmaf(a[1] + h1, g1, e1));
                        float x10 = __sinf(30.0f * fmaf(a[2] + h0, g0, e0));
                        float x11 = __sinf(30.0f * fmaf(a[3] + h1, g1, e1));
                        uint32_t lo0, hi0 = pack_split(x00, x01, lo0);
                        uint32_t lo1, hi1 = pack_split(x10, x11, lo1);
                        *reinterpret_cast<uint32_t*>(Ah + r0 * A_PITCH + n0 * 2)       = hi0;
                        *reinterpret_cast<uint32_t*>(Al + r0 * A_PITCH + n0 * 2)       = lo0;
                        *reinterpret_cast<uint32_t*>(Ah + (r0 + 8) * A_PITCH + n0 * 2) = hi1;
                        *reinterpret_cast<uint32_t*>(Al + (r0 + 8) * A_PITCH + n0 * 2) = lo1;
                        a[0] = 0.f; a[1] = 0.f; a[2] = 0.f; a[3] = 0.f;
                    }
                }
            } else {
                // final layer: FiLM + sin -> output head partials
                float pacc[4][3];
                #pragma unroll
                for (int i = 0; i < 4; ++i)
                    #pragma unroll
                    for (int c = 0; c < 3; ++c) pacc[i][c] = 0.f;
                #pragma unroll
                for (int mt = 0; mt < 2; ++mt) {
                    #pragma unroll
                    for (int nt = 0; nt < 16; ++nt) {
                        const int n0 = 128 * wn + 8 * nt + 2 * (L & 3);
                        const float g0 = 1.0f + film[n0], g1 = 1.0f + film[n0 + 1];
                        const float e0 = film[256 + n0],  e1 = film[256 + n0 + 1];
                        const float h0 = film[512 + n0],  h1 = film[512 + n0 + 1];
                        float* a = acc[mt][nt];
                        float x00 = __sinf(30.0f * fmaf(a[0] + h0, g0, e0));
                        float x01 = __sinf(30.0f * fmaf(a[1] + h1, g1, e1));
                        float x10 = __sinf(30.0f * fmaf(a[2] + h0, g0, e0));
                        float x11 = __sinf(30.0f * fmaf(a[3] + h1, g1, e1));
                        #pragma unroll
                        for (int c = 0; c < 3; ++c) {
                            const float wl0 = Wlg[n0 * 3 + c];
                            const float wl1 = Wlg[(n0 + 1) * 3 + c];
                            pacc[mt * 2][c]     = fmaf(x00, wl0, fmaf(x01, wl1, pacc[mt * 2][c]));
                            pacc[mt * 2 + 1][c] = fmaf(x10, wl0, fmaf(x11, wl1, pacc[mt * 2 + 1][c]));
                        }
                    }
                }
                // reduce over the 4 lanes covering each row
                #pragma unroll
                for (int i = 0; i < 4; ++i)
                    #pragma unroll
                    for (int c = 0; c < 3; ++c) {
                        pacc[i][c] += __shfl_xor_sync(~0u, pacc[i][c], 1);
                        pacc[i][c] += __shfl_xor_sync(~0u, pacc[i][c], 2);
                    }
                if ((L & 3) == 0) {
                    #pragma unroll
                    for (int mt = 0; mt < 2; ++mt) {
                        const int r0 = 32 * wm + 16 * mt + (L >> 2);
                        #pragma unroll
                        for (int c = 0; c < 3; ++c) {
                            red[r0 * 6 + wn * 3 + c]       = pacc[mt * 2][c];
                            red[(r0 + 8) * 6 + wn * 3 + c] = pacc[mt * 2 + 1][c];
                        }
                    }
                }
            }
        }
    }

    __syncthreads();
    if (t < 128) {
        float* op = out + ((size_t)(b * 4096 + m_base + t)) * 3;
        #pragma unroll
        for (int c = 0; c < 3; ++c)
            op[c] = red[t * 6 + c] + red[t * 6 + 3 + c] + blg[c];
    }
}

// =================================================================
extern "C" void kernel_launch(void* const* d_in, const int* in_sizes, int n_in,
                              void* d_out, int out_size) {
    const float* coords  = (const float*)d_in[0];
    const int*   lidx    = (const int*)  d_in[1];
    const float* latents = (const float*)d_in[2];
    const float* emb     = (const float*)d_in[3];
    const float* mod_W   = (const float*)d_in[4];
    const float* mod_b   = (const float*)d_in[5];
    const float* W0      = (const float*)d_in[6];
    const float* b0      = (const float*)d_in[7];
    const float* Wh      = (const float*)d_in[8];
    const float* bh      = (const float*)d_in[9];
    const float* Wl      = (const float*)d_in[10];
    const float* bl      = (const float*)d_in[11];
    float* out = (float*)d_out;

    prep_kernel<<<512, 256>>>(Wh);
    vq_kernel<<<16, 1024>>>(lidx, latents, emb);
    mods_kernel<<<dim3(5, 4), 128>>>(mod_W, mod_b);
    loss_kernel<<<1, 32>>>(out, out_size);

    const int smem = 226304;
    cudaFuncSetAttribute(dec_mma, cudaFuncAttributeMaxDynamicSharedMemorySize, smem);
    dec_mma<<<dim3(32, 16), 256, smem>>>(coords, W0, b0, bh, Wl, bl, out);
}

// round 9
// speedup vs baseline: 1.7152x; 1.0739x over previous
#include <cuda_runtime.h>
#include <cuda_bf16.h>
#include <cstdint>

typedef unsigned long long ull;

// ---------------- scratch (no allocation allowed) ----------------
__device__ float g_mods[16 * 5 * 512];         // [b][layer][gam|bet]
__device__ float g_loss[16];                   // per-b summed loss
// transposed + bf16 hi/lo split weights:
// [layer][plane hi/lo][n=256][k=256] bf16  -> 4 * 2 * 131072 bytes
__device__ unsigned char g_B[4 * 2 * 131072];

// ---------------- helpers ----------------
__device__ __forceinline__ uint32_t smem_u32(const void* p) {
    uint32_t a;
    asm("{ .reg .u64 t; cvta.to.shared.u64 t, %1; cvt.u32.u64 %0, t; }"
        : "=r"(a) : "l"(p));
    return a;
}
__device__ __forceinline__ void cp16(void* dst, const void* src) {
    unsigned s = smem_u32(dst);
    asm volatile("cp.async.ca.shared.global [%0], [%1], 16;" :: "r"(s), "l"(src));
}
__device__ __forceinline__ void ldm_x4(uint32_t* r, const void* p) {
    uint32_t a = smem_u32(p);
    asm volatile("ldmatrix.sync.aligned.m8n8.x4.shared.b16 {%0,%1,%2,%3}, [%4];"
                 : "=r"(r[0]), "=r"(r[1]), "=r"(r[2]), "=r"(r[3]) : "r"(a));
}
__device__ __forceinline__ void mma16816(float* c, const uint32_t* a, const uint32_t* b) {
    asm volatile(
        "mma.sync.aligned.m16n8k16.row.col.f32.bf16.bf16.f32 "
        "{%0,%1,%2,%3}, {%4,%5,%6,%7}, {%8,%9}, {%0,%1,%2,%3};"
        : "+f"(c[0]), "+f"(c[1]), "+f"(c[2]), "+f"(c[3])
        : "r"(a[0]), "r"(a[1]), "r"(a[2]), "r"(a[3]), "r"(b[0]), "r"(b[1]));
}
__device__ __forceinline__ uint32_t pack_split(float x0, float x1, uint32_t& lo_out) {
    __nv_bfloat16 h0 = __float2bfloat16(x0);
    __nv_bfloat16 h1 = __float2bfloat16(x1);
    __nv_bfloat16 l0 = __float2bfloat16(x0 - __bfloat162float(h0));
    __nv_bfloat16 l1 = __float2bfloat16(x1 - __bfloat162float(h1));
    lo_out = ((uint32_t)__bfloat16_as_ushort(l1) << 16) | __bfloat16_as_ushort(l0);
    return ((uint32_t)__bfloat16_as_ushort(h1) << 16) | __bfloat16_as_ushort(h0);
}

// =================================================================
// Kernel 1: residual VQ + fused FiLM mods. grid=16, 1024 thr.
// =================================================================
__global__ __launch_bounds__(1024)
void vq_kernel(const int* __restrict__ lidx,
               const float* __restrict__ latents,
               const float* __restrict__ emb,
               const float* __restrict__ mod_W,
               const float* __restrict__ mod_b) {
    __shared__ float r[256];
    __shared__ float q[256];
    __shared__ float wsc[32];
    __shared__ int   wci[32];
    __shared__ float s_d, s_r2;
    __shared__ int   s_c;

    const int b = blockIdx.x, t = threadIdx.x;
    const int lane = t & 31, wid = t >> 5;

    if (t < 256) {
        const float* lp = latents + (size_t)lidx[b] * 1024;
        float z = lp[t] + lp[256 + t] + lp[512 + t] + lp[768 + t];
        r[t] = z; q[t] = 0.f;
    }
    __syncthreads();

    if (wid == 0) {
        float rz = 0.f;
        #pragma unroll
        for (int j = 0; j < 8; ++j) { float v = r[lane * 8 + j]; rz = fmaf(v, v, rz); }
        #pragma unroll
        for (int o = 16; o; o >>= 1) rz += __shfl_xor_sync(~0u, rz, o);
        if (lane == 0) s_r2 = rz;
    }
    float loss = 0.f;
    __syncthreads();

    for (int s = 0; s < 4; ++s) {
        float4 rj0 = reinterpret_cast<const float4*>(r)[lane * 2];
        float4 rj1 = reinterpret_cast<const float4*>(r)[lane * 2 + 1];
        float best = -3.4e38f;
        int   bi   = 0;
        const int c0 = wid * 32;
        #pragma unroll 4
        for (int i = 0; i < 32; ++i) {
            const int c = c0 + i;
            const float4* E4 = reinterpret_cast<const float4*>(emb)
                               + (size_t)(s * 1024 + c) * 64 + lane * 2;
            float4 e0 = E4[0], e1 = E4[1];
            float p = e0.x * rj0.x + e0.y * rj0.y + e0.z * rj0.z + e0.w * rj0.w
                    + e1.x * rj1.x + e1.y * rj1.y + e1.z * rj1.z + e1.w * rj1.w;
            #pragma unroll
            for (int o = 16; o; o >>= 1) p += __shfl_xor_sync(~0u, p, o);
            if (p > best) { best = p; bi = c; }
        }
        if (lane == 0) { wsc[wid] = best; wci[wid] = bi; }
        __syncthreads();
        if (wid == 0) {
            float v = wsc[lane]; int ci = wci[lane];
            #pragma unroll
            for (int o = 16; o; o >>= 1) {
                float ov = __shfl_down_sync(~0u, v,  o);
                int   oi = __shfl_down_sync(~0u, ci, o);
                if (ov > v || (ov == v && oi < ci)) { v = ov; ci = oi; }
            }
            if (lane == 0) { s_c = ci; s_d = 1.0f - 2.0f * v; }
        }
        __syncthreads();
        if (t == 0) { loss += s_d + s_r2; s_r2 += s_d; }
        const int cmin = s_c;
        if (t < 256) {
            float e = emb[((size_t)s * 1024 + cmin) * 256 + t];
            q[t] += e; r[t] -= e;
        }
        __syncthreads();
    }
    if (t == 0) g_loss[b] = loss;

    // ---- fused FiLM mods for this b: g_mods[b][l][h] ----
    for (int i = t; i < 2560; i += 1024) {
        const int l = i >> 9, h = i & 511;
        float a = mod_b[l * 512 + h];
        const float* Wp = mod_W + (size_t)l * 131072 + h;
        #pragma unroll 4
        for (int d = 0; d < 256; ++d)
            a = fmaf(q[d], Wp[(size_t)d * 512], a);
        g_mods[b * 2560 + i] = a;
    }
}

// =================================================================
// Kernel 2: vq_loss finalize
// =================================================================
__global__ void loss_kernel(float* out, int out_size) {
    if (threadIdx.x == 0) {
        float s = 0.f;
        #pragma unroll
        for (int i = 0; i < 16; ++i) s += g_loss[i];
        out[out_size - 1] = s * (1.0f / 65536.0f);
    }
}

// =================================================================
// Kernel 3: weight prep — Wt[n][k] bf16 hi/lo planes (131072 B each)
// =================================================================
__global__ __launch_bounds__(256)
void prep_kernel(const float* __restrict__ Whg) {
    const int i = blockIdx.x * 256 + threadIdx.x;   // 131072 total
    const int layer = i >> 15;
    const int kp    = (i >> 8) & 127;
    const int n     = i & 255;
    const int k     = kp * 2;
    float w0 = Whg[(size_t)layer * 65536 + (size_t)k * 256 + n];
    float w1 = Whg[(size_t)layer * 65536 + (size_t)(k + 1) * 256 + n];
    uint32_t lo, hi = pack_split(w0, w1, lo);
    unsigned char* base = g_B + (size_t)layer * 262144;
    *reinterpret_cast<uint32_t*>(base + n * 512 + k * 2)          = hi;
    *reinterpret_cast<uint32_t*>(base + 131072 + n * 512 + k * 2) = lo;
}

// =================================================================
// Kernel 4: HMMA SIREN decoder.
// grid (64 tiles, 16 b), 256 thr, M_TILE=64 (6.92 waves, 98.8% eff).
// A planes: [64m][256k] bf16 hi/lo, pitch 528B.
// B: 32-k chunks [256n][32k] hi/lo, pitch 80B, double-buffered cp.async.
// Warps 2m x 4n; warp tile 32m x 64n. B loaded via ldmatrix.x4
// (two n-tiles per instr). 3-term: Ah*Bh + Al*Bh + Ah*Bl.
// =================================================================
#define A_PITCH 528
#define A_PLANE 33792
#define B_ROW   80
#define B_PLANE 20480
#define B_BUF   40960

__global__ __launch_bounds__(256, 1)
void dec_mma(const float* __restrict__ coords,
             const float* __restrict__ W0g,
             const float* __restrict__ b0g,
             const float* __restrict__ bhg,
             const float* __restrict__ Wlg,
             const float* __restrict__ blg,
             float* __restrict__ out) {
    extern __shared__ char smc[];
    char*  Ah   = smc;                         // 33792
    char*  Al   = smc + A_PLANE;               // 33792
    char*  Bb   = smc + 2 * A_PLANE;           // 81920 (2 bufs x 2 planes)
    float* w0s  = (float*)(smc + 149504);      // 768 f
    float* film = (float*)(smc + 152576);      // 768 f (gam|bet|bh, one layer)
    float* red  = (float*)(smc + 155648);      // 64*12 f
    // total 158720 B

    const int b      = blockIdx.y;
    const int m_base = blockIdx.x * 64;
    const int t  = threadIdx.x;
    const int L  = t & 31;
    const int wid = t >> 5;
    const int wm = wid >> 2;       // 0..1 (m)
    const int wn = wid & 3;        // 0..3 (n)

    // stage W0/b0
    for (int i = t; i < 768; i += 256) w0s[i] = (i < 512) ? W0g[i] : b0g[i - 512];

    // prefetch B chunk 0 (layer 0, kc 0) into buf 0
    {
        const unsigned char* s0 = g_B + t * 512;
        char* d0 = Bb + t * B_ROW;
        #pragma unroll
        for (int j = 0; j < 4; ++j) cp16(d0 + j * 16, s0 + j * 16);
        const unsigned char* s1 = s0 + 131072;
        char* d1 = d0 + B_PLANE;
        #pragma unroll
        for (int j = 0; j < 4; ++j) cp16(d1 + j * 16, s1 + j * 16);
        asm volatile("cp.async.commit_group;");
    }
    __syncthreads();

    // ---- layer 0: fill A planes (row m = t&63, quarter q = t>>6) ----
    {
        const int m = t & 63, qd = t >> 6;
        const float2 c2 = reinterpret_cast<const float2*>(coords)[b * 4096 + m_base + m];
        char* rowH = Ah + m * A_PITCH;
        char* rowL = Al + m * A_PITCH;
        #pragma unroll 4
        for (int n = qd * 64; n < qd * 64 + 64; n += 2) {
            float p0 = fmaf(c2.x, w0s[n],     fmaf(c2.y, w0s[256 + n],     w0s[512 + n]));
            float p1 = fmaf(c2.x, w0s[n + 1], fmaf(c2.y, w0s[256 + n + 1], w0s[512 + n + 1]));
            float x0 = __sinf(30.0f * p0);
            float x1 = __sinf(30.0f * p1);
            uint32_t lo, hi = pack_split(x0, x1, lo);
            *reinterpret_cast<uint32_t*>(rowH + n * 2) = hi;
            *reinterpret_cast<uint32_t*>(rowL + n * 2) = lo;
        }
    }

    float acc[2][8][4];
    #pragma unroll
    for (int mt = 0; mt < 2; ++mt)
        #pragma unroll
        for (int nt = 0; nt < 8; ++nt)
            #pragma unroll
            for (int j = 0; j < 4; ++j) acc[mt][nt][j] = 0.f;

    // 32 iterations: 4 layers x 8 chunks of 32 k
    for (int p = 0; p < 32; ++p) {
        __syncthreads();   // prev compute done; epilogue A writes visible

        if (p < 31) {      // prefetch chunk p+1
            const int pl = (p + 1) >> 3, pk = (p + 1) & 7;
            const unsigned char* s0 = g_B + (size_t)pl * 262144 + t * 512 + pk * 64;
            char* d0 = Bb + ((p + 1) & 1) * B_BUF + t * B_ROW;
            #pragma unroll
            for (int j = 0; j < 4; ++j) cp16(d0 + j * 16, s0 + j * 16);
            const unsigned char* s1 = s0 + 131072;
            char* d1 = d0 + B_PLANE;
            #pragma unroll
            for (int j = 0; j < 4; ++j) cp16(d1 + j * 16, s1 + j * 16);
            asm volatile("cp.async.commit_group;");
            asm volatile("cp.async.wait_group 1;");
        } else {
            asm volatile("cp.async.wait_group 0;");
        }
        __syncthreads();   // chunk p visible

        const int l   = p >> 3;
        const int k0g = (p & 7) * 32;

        if ((p & 7) == 7) {   // preload film for this layer (read after next sync)
            for (int i = t; i < 768; i += 256)
                film[i] = (i < 512) ? g_mods[b * 2560 + 512 + l * 512 + i]
                                    : bhg[l * 256 + (i - 512)];
        }

        const char* Bbuf = Bb + (p & 1) * B_BUF;
        #pragma unroll
        for (int kt = 0; kt < 2; ++kt) {
            uint32_t ah[2][4], al[2][4];
            const int acol = (k0g + kt * 16 + (L >> 4) * 8) * 2;
            #pragma unroll
            for (int mt = 0; mt < 2; ++mt) {
                const int arow = 32 * wm + 16 * mt + (L & 15);
                ldm_x4(ah[mt], Ah + arow * A_PITCH + acol);
                ldm_x4(al[mt], Al + arow * A_PITCH + acol);
            }
            #pragma unroll
            for (int ntp = 0; ntp < 4; ++ntp) {
                // x4 loads two n-tiles (2*ntp, 2*ntp+1), k16 each:
                // lanes 0-7: ntA/khalf0, 8-15: ntA/khalf1, 16-23: ntB/khalf0, 24-31: ntB/khalf1
                uint32_t bh4[4], bl4[4];
                const int nt_sel = 2 * ntp + (L >> 4);
                const int khalf  = (L >> 3) & 1;
                const unsigned boff = (unsigned)(64 * wn + 8 * nt_sel + (L & 7)) * B_ROW
                                    + (unsigned)(kt * 16 + khalf * 8) * 2;
                ldm_x4(bh4, Bbuf + boff);
                ldm_x4(bl4, Bbuf + B_PLANE + boff);
                #pragma unroll
                for (int mt = 0; mt < 2; ++mt) {
                    mma16816(acc[mt][2 * ntp],     ah[mt], bh4);
                    mma16816(acc[mt][2 * ntp],     al[mt], bh4);
                    mma16816(acc[mt][2 * ntp],     ah[mt], bl4);
                    mma16816(acc[mt][2 * ntp + 1], ah[mt], bh4 + 2);
                    mma16816(acc[mt][2 * ntp + 1], al[mt], bh4 + 2);
                    mma16816(acc[mt][2 * ntp + 1], ah[mt], bl4 + 2);
                }
            }
        }

        if ((p & 7) == 7) {
            __syncthreads();   // all compute done; film visible
            if (l < 3) {
                // FiLM + sin -> A planes; zero acc
                #pragma unroll
                for (int mt = 0; mt < 2; ++mt) {
                    const int r0 = 32 * wm + 16 * mt + (L >> 2);
                    #pragma unroll
                    for (int nt = 0; nt < 8; ++nt) {
                        const int n0 = 64 * wn + 8 * nt + 2 * (L & 3);
                        const float g0 = 1.0f + film[n0], g1 = 1.0f + film[n0 + 1];
                        const float e0 = film[256 + n0],  e1 = film[256 + n0 + 1];
                        const float h0 = film[512 + n0],  h1 = film[512 + n0 + 1];
                        float* a = acc[mt][nt];
                        float x00 = __sinf(30.0f * fmaf(a[0] + h0, g0, e0));
                        float x01 = __sinf(30.0f * fmaf(a[1] + h1, g1, e1));
                        float x10 = __sinf(30.0f * fmaf(a[2] + h0, g0, e0));
                        float x11 = __sinf(30.0f * fmaf(a[3] + h1, g1, e1));
                        uint32_t lo0, hi0 = pack_split(x00, x01, lo0);
                        uint32_t lo1, hi1 = pack_split(x10, x11, lo1);
                        *reinterpret_cast<uint32_t*>(Ah + r0 * A_PITCH + n0 * 2)       = hi0;
                        *reinterpret_cast<uint32_t*>(Al + r0 * A_PITCH + n0 * 2)       = lo0;
                        *reinterpret_cast<uint32_t*>(Ah + (r0 + 8) * A_PITCH + n0 * 2) = hi1;
                        *reinterpret_cast<uint32_t*>(Al + (r0 + 8) * A_PITCH + n0 * 2) = lo1;
                        a[0] = 0.f; a[1] = 0.f; a[2] = 0.f; a[3] = 0.f;
                    }
                }
            } else {
                // final layer: FiLM + sin -> output head partials
                float pacc[4][3];
                #pragma unroll
                for (int i = 0; i < 4; ++i)
                    #pragma unroll
                    for (int c = 0; c < 3; ++c) pacc[i][c] = 0.f;
                #pragma unroll
                for (int mt = 0; mt < 2; ++mt) {
                    #pragma unroll
                    for (int nt = 0; nt < 8; ++nt) {
                        const int n0 = 64 * wn + 8 * nt + 2 * (L & 3);
                        const float g0 = 1.0f + film[n0], g1 = 1.0f + film[n0 + 1];
                        const float e0 = film[256 + n0],  e1 = film[256 + n0 + 1];
                        const float h0 = film[512 + n0],  h1 = film[512 + n0 + 1];
                        float* a = acc[mt][nt];
                        float x00 = __sinf(30.0f * fmaf(a[0] + h0, g0, e0));
                        float x01 = __sinf(30.0f * fmaf(a[1] + h1, g1, e1));
                        float x10 = __sinf(30.0f * fmaf(a[2] + h0, g0, e0));
                        float x11 = __sinf(30.0f * fmaf(a[3] + h1, g1, e1));
                        #pragma unroll
                        for (int c = 0; c < 3; ++c) {
                            const float wl0 = Wlg[n0 * 3 + c];
                            const float wl1 = Wlg[(n0 + 1) * 3 + c];
                            pacc[mt * 2][c]     = fmaf(x00, wl0, fmaf(x01, wl1, pacc[mt * 2][c]));
                            pacc[mt * 2 + 1][c] = fmaf(x10, wl0, fmaf(x11, wl1, pacc[mt * 2 + 1][c]));
                        }
                    }
                }
                #pragma unroll
                for (int i = 0; i < 4; ++i)
                    #pragma unroll
                    for (int c = 0; c < 3; ++c) {
                        pacc[i][c] += __shfl_xor_sync(~0u, pacc[i][c], 1);
                        pacc[i][c] += __shfl_xor_sync(~0u, pacc[i][c], 2);
                    }
                if ((L & 3) == 0) {
                    #pragma unroll
                    for (int mt = 0; mt < 2; ++mt) {
                        const int r0 = 32 * wm + 16 * mt + (L >> 2);
                        #pragma unroll
                        for (int c = 0; c < 3; ++c) {
                            red[r0 * 12 + wn * 3 + c]       = pacc[mt * 2][c];
                            red[(r0 + 8) * 12 + wn * 3 + c] = pacc[mt * 2 + 1][c];
                        }
                    }
                }
            }
        }
    }

    __syncthreads();
    if (t < 64) {
        float* op = out + ((size_t)(b * 4096 + m_base + t)) * 3;
        #pragma unroll
        for (int c = 0; c < 3; ++c)
            op[c] = (red[t * 12 + c] + red[t * 12 + 3 + c])
                  + (red[t * 12 + 6 + c] + red[t * 12 + 9 + c]) + blg[c];
    }
}

// =================================================================
extern "C" void kernel_launch(void* const* d_in, const int* in_sizes, int n_in,
                              void* d_out, int out_size) {
    const float* coords  = (const float*)d_in[0];
    const int*   lidx    = (const int*)  d_in[1];
    const float* latents = (const float*)d_in[2];
    const float* emb     = (const float*)d_in[3];
    const float* mod_W   = (const float*)d_in[4];
    const float* mod_b   = (const float*)d_in[5];
    const float* W0      = (const float*)d_in[6];
    const float* b0      = (const float*)d_in[7];
    const float* Wh      = (const float*)d_in[8];
    const float* bh      = (const float*)d_in[9];
    const float* Wl      = (const float*)d_in[10];
    const float* bl      = (const float*)d_in[11];
    float* out = (float*)d_out;

    prep_kernel<<<512, 256>>>(Wh);
    vq_kernel<<<16, 1024>>>(lidx, latents, emb, mod_W, mod_b);
    loss_kernel<<<1, 32>>>(out, out_size);

    const int smem = 158720;
    cudaFuncSetAttribute(dec_mma, cudaFuncAttributeMaxDynamicSharedMemorySize, smem);
    dec_mma<<<dim3(64, 16), 256, smem>>>(coords, W0, b0, bh, Wl, bl, out);
}

// round 10
// speedup vs baseline: 1.8651x; 1.0874x over previous
#include <cuda_runtime.h>
#include <cuda_bf16.h>
#include <cstdint>

typedef unsigned long long ull;

// ---------------- scratch (no allocation allowed) ----------------
__device__ float g_mods[16 * 5 * 512];         // [b][layer][gam|bet]
__device__ float g_loss[16];                   // per-b summed loss
// transposed + bf16 hi/lo split weights:
// [layer][plane hi/lo][n=256][k=256] bf16  -> 4 * 2 * 131072 bytes
__device__ unsigned char g_B[4 * 2 * 131072];

// ---------------- helpers ----------------
__device__ __forceinline__ uint32_t smem_u32(const void* p) {
    uint32_t a;
    asm("{ .reg .u64 t; cvta.to.shared.u64 t, %1; cvt.u32.u64 %0, t; }"
        : "=r"(a) : "l"(p));
    return a;
}
__device__ __forceinline__ void cp16(void* dst, const void* src) {
    unsigned s = smem_u32(dst);
    asm volatile("cp.async.ca.shared.global [%0], [%1], 16;" :: "r"(s), "l"(src));
}
__device__ __forceinline__ void ldm_x4(uint32_t* r, const void* p) {
    uint32_t a = smem_u32(p);
    asm volatile("ldmatrix.sync.aligned.m8n8.x4.shared.b16 {%0,%1,%2,%3}, [%4];"
                 : "=r"(r[0]), "=r"(r[1]), "=r"(r[2]), "=r"(r[3]) : "r"(a));
}
__device__ __forceinline__ void mma16816(float* c, const uint32_t* a, const uint32_t* b) {
    asm volatile(
        "mma.sync.aligned.m16n8k16.row.col.f32.bf16.bf16.f32 "
        "{%0,%1,%2,%3}, {%4,%5,%6,%7}, {%8,%9}, {%0,%1,%2,%3};"
        : "+f"(c[0]), "+f"(c[1]), "+f"(c[2]), "+f"(c[3])
        : "r"(a[0]), "r"(a[1]), "r"(a[2]), "r"(a[3]), "r"(b[0]), "r"(b[1]));
}
__device__ __forceinline__ uint32_t pack_split(float x0, float x1, uint32_t& lo_out) {
    __nv_bfloat16 h0 = __float2bfloat16(x0);
    __nv_bfloat16 h1 = __float2bfloat16(x1);
    __nv_bfloat16 l0 = __float2bfloat16(x0 - __bfloat162float(h0));
    __nv_bfloat16 l1 = __float2bfloat16(x1 - __bfloat162float(h1));
    lo_out = ((uint32_t)__bfloat16_as_ushort(l1) << 16) | __bfloat16_as_ushort(l0);
    return ((uint32_t)__bfloat16_as_ushort(h1) << 16) | __bfloat16_as_ushort(h0);
}

// =================================================================
// Kernel 1: residual VQ + fused FiLM mods. grid=16, 1024 thr.
// =================================================================
__global__ __launch_bounds__(1024)
void vq_kernel(const int* __restrict__ lidx,
               const float* __restrict__ latents,
               const float* __restrict__ emb,
               const float* __restrict__ mod_W,
               const float* __restrict__ mod_b) {
    __shared__ float r[256];
    __shared__ float q[256];
    __shared__ float wsc[32];
    __shared__ int   wci[32];
    __shared__ float s_d, s_r2;
    __shared__ int   s_c;

    const int b = blockIdx.x, t = threadIdx.x;
    const int lane = t & 31, wid = t >> 5;

    if (t < 256) {
        const float* lp = latents + (size_t)lidx[b] * 1024;
        float z = lp[t] + lp[256 + t] + lp[512 + t] + lp[768 + t];
        r[t] = z; q[t] = 0.f;
    }
    __syncthreads();

    if (wid == 0) {
        float rz = 0.f;
        #pragma unroll
        for (int j = 0; j < 8; ++j) { float v = r[lane * 8 + j]; rz = fmaf(v, v, rz); }
        #pragma unroll
        for (int o = 16; o; o >>= 1) rz += __shfl_xor_sync(~0u, rz, o);
        if (lane == 0) s_r2 = rz;
    }
    float loss = 0.f;
    __syncthreads();

    for (int s = 0; s < 4; ++s) {
        float4 rj0 = reinterpret_cast<const float4*>(r)[lane * 2];
        float4 rj1 = reinterpret_cast<const float4*>(r)[lane * 2 + 1];
        float best = -3.4e38f;
        int   bi   = 0;
        const int c0 = wid * 32;
        #pragma unroll 4
        for (int i = 0; i < 32; ++i) {
            const int c = c0 + i;
            const float4* E4 = reinterpret_cast<const float4*>(emb)
                               + (size_t)(s * 1024 + c) * 64 + lane * 2;
            float4 e0 = E4[0], e1 = E4[1];
            float p = e0.x * rj0.x + e0.y * rj0.y + e0.z * rj0.z + e0.w * rj0.w
                    + e1.x * rj1.x + e1.y * rj1.y + e1.z * rj1.z + e1.w * rj1.w;
            #pragma unroll
            for (int o = 16; o; o >>= 1) p += __shfl_xor_sync(~0u, p, o);
            if (p > best) { best = p; bi = c; }
        }
        if (lane == 0) { wsc[wid] = best; wci[wid] = bi; }
        __syncthreads();
        if (wid == 0) {
            float v = wsc[lane]; int ci = wci[lane];
            #pragma unroll
            for (int o = 16; o; o >>= 1) {
                float ov = __shfl_down_sync(~0u, v,  o);
                int   oi = __shfl_down_sync(~0u, ci, o);
                if (ov > v || (ov == v && oi < ci)) { v = ov; ci = oi; }
            }
            if (lane == 0) { s_c = ci; s_d = 1.0f - 2.0f * v; }
        }
        __syncthreads();
        if (t == 0) { loss += s_d + s_r2; s_r2 += s_d; }
        const int cmin = s_c;
        if (t < 256) {
            float e = emb[((size_t)s * 1024 + cmin) * 256 + t];
            q[t] += e; r[t] -= e;
        }
        __syncthreads();
    }
    if (t == 0) g_loss[b] = loss;

    // ---- fused FiLM mods for this b ----
    for (int i = t; i < 2560; i += 1024) {
        const int l = i >> 9, h = i & 511;
        float a = mod_b[l * 512 + h];
        const float* Wp = mod_W + (size_t)l * 131072 + h;
        #pragma unroll 4
        for (int d = 0; d < 256; ++d)
            a = fmaf(q[d], Wp[(size_t)d * 512], a);
        g_mods[b * 2560 + i] = a;
    }
}

// =================================================================
// Kernel 2: vq_loss finalize
// =================================================================
__global__ void loss_kernel(float* out, int out_size) {
    if (threadIdx.x == 0) {
        float s = 0.f;
        #pragma unroll
        for (int i = 0; i < 16; ++i) s += g_loss[i];
        out[out_size - 1] = s * (1.0f / 65536.0f);
    }
}

// =================================================================
// Kernel 3: weight prep — Wt[n][k] bf16 hi/lo planes (131072 B each)
// =================================================================
__global__ __launch_bounds__(256)
void prep_kernel(const float* __restrict__ Whg) {
    const int i = blockIdx.x * 256 + threadIdx.x;   // 131072 total
    const int layer = i >> 15;
    const int kp    = (i >> 8) & 127;
    const int n     = i & 255;
    const int k     = kp * 2;
    float w0 = Whg[(size_t)layer * 65536 + (size_t)k * 256 + n];
    float w1 = Whg[(size_t)layer * 65536 + (size_t)(k + 1) * 256 + n];
    uint32_t lo, hi = pack_split(w0, w1, lo);
    unsigned char* base = g_B + (size_t)layer * 262144;
    *reinterpret_cast<uint32_t*>(base + n * 512 + k * 2)          = hi;
    *reinterpret_cast<uint32_t*>(base + 131072 + n * 512 + k * 2) = lo;
}

// =================================================================
// Kernel 4: HMMA SIREN decoder.
// grid (64 tiles, 16 b), 256 thr, M_TILE=64, 2 CTAs/SM (128 regs).
// A planes: [64m][256k] bf16 hi/lo, pitch 528B.
// B: 16-k chunks [256n][16k] hi/lo, XOR-swizzled 32B pitch,
//    double-buffered cp.async (smem 109.6KB total).
// Warps 2m x 4n; warp tile 32m x 64n; B via ldmatrix.x4.
// 3-term: Ah*Bh + Al*Bh + Ah*Bl.
// =================================================================
#define A_PITCH 528
#define A_PLANE 33792
#define B_PLANE 8192
#define B_BUF   16384

__global__ __launch_bounds__(256, 2)
void dec_mma(const float* __restrict__ coords,
             const float* __restrict__ W0g,
             const float* __restrict__ b0g,
             const float* __restrict__ bhg,
             const float* __restrict__ Wlg,
             const float* __restrict__ blg,
             float* __restrict__ out) {
    extern __shared__ char smc[];
    char*  Ah   = smc;                         // 33792
    char*  Al   = smc + A_PLANE;               // 33792
    char*  Bb   = smc + 2 * A_PLANE;           // 32768 (2 bufs x 2 planes)
    float* w0s  = (float*)(smc + 100352);      // 768 f
    float* film = (float*)(smc + 103424);      // 768 f (gam|bet|bh, one layer)
    float* red  = (float*)(smc + 106496);      // 64*12 f
    // total 109568 B

    const int b      = blockIdx.y;
    const int m_base = blockIdx.x * 64;
    const int t  = threadIdx.x;
    const int L  = t & 31;
    const int wid = t >> 5;
    const int wm = wid >> 2;       // 0..1 (m)
    const int wn = wid & 3;        // 0..3 (n)

    // stage W0/b0
    for (int i = t; i < 768; i += 256) w0s[i] = (i < 512) ? W0g[i] : b0g[i - 512];

    // prefetch B chunk 0 (layer 0, k0) into buf 0 (swizzled dst)
    {
        #pragma unroll
        for (int j = 0; j < 4; ++j) {
            const int c = t + j * 256;          // 0..1023
            const int plane = c >> 9;
            const int cc = c & 511;
            const int r = cc >> 1, h = cc & 1;
            const unsigned char* s = g_B + plane * 131072 + r * 512 + h * 16;
            char* d = Bb + plane * B_PLANE + r * 32 + ((h * 16) ^ (((r >> 2) & 1) * 16));
            cp16(d, s);
        }
        asm volatile("cp.async.commit_group;");
    }
    __syncthreads();

    // ---- layer 0: fill A planes (row m = t&63, quarter q = t>>6) ----
    {
        const int m = t & 63, qd = t >> 6;
        const float2 c2 = reinterpret_cast<const float2*>(coords)[b * 4096 + m_base + m];
        char* rowH = Ah + m * A_PITCH;
        char* rowL = Al + m * A_PITCH;
        #pragma unroll 4
        for (int n = qd * 64; n < qd * 64 + 64; n += 2) {
            float p0 = fmaf(c2.x, w0s[n],     fmaf(c2.y, w0s[256 + n],     w0s[512 + n]));
            float p1 = fmaf(c2.x, w0s[n + 1], fmaf(c2.y, w0s[256 + n + 1], w0s[512 + n + 1]));
            float x0 = __sinf(30.0f * p0);
            float x1 = __sinf(30.0f * p1);
            uint32_t lo, hi = pack_split(x0, x1, lo);
            *reinterpret_cast<uint32_t*>(rowH + n * 2) = hi;
            *reinterpret_cast<uint32_t*>(rowL + n * 2) = lo;
        }
    }

    float acc[2][8][4];
    #pragma unroll
    for (int mt = 0; mt < 2; ++mt)
        #pragma unroll
        for (int nt = 0; nt < 8; ++nt)
            #pragma unroll
            for (int j = 0; j < 4; ++j) acc[mt][nt][j] = 0.f;

    // 64 iterations: 4 layers x 16 chunks of 16 k
    for (int p = 0; p < 64; ++p) {
        __syncthreads();   // prev compute done; epilogue A writes visible

        if (p < 63) {      // prefetch chunk p+1
            const int pl = (p + 1) >> 4, pk = (p + 1) & 15;
            const unsigned char* srcb = g_B + (size_t)pl * 262144 + pk * 32;
            char* dstb = Bb + ((p + 1) & 1) * B_BUF;
            #pragma unroll
            for (int j = 0; j < 4; ++j) {
                const int c = t + j * 256;
                const int plane = c >> 9;
                const int cc = c & 511;
                const int r = cc >> 1, h = cc & 1;
                const unsigned char* s = srcb + plane * 131072 + r * 512 + h * 16;
                char* d = dstb + plane * B_PLANE + r * 32 + ((h * 16) ^ (((r >> 2) & 1) * 16));
                cp16(d, s);
            }
            asm volatile("cp.async.commit_group;");
            asm volatile("cp.async.wait_group 1;");
        } else {
            asm volatile("cp.async.wait_group 0;");
        }
        __syncthreads();   // chunk p visible

        const int l   = p >> 4;
        const int k0g = (p & 15) * 16;

        if ((p & 15) == 15) {   // preload film for this layer (read after next sync)
            for (int i = t; i < 768; i += 256)
                film[i] = (i < 512) ? g_mods[b * 2560 + 512 + l * 512 + i]
                                    : bhg[l * 256 + (i - 512)];
        }

        const char* Bbuf = Bb + (p & 1) * B_BUF;
        {
            uint32_t ah[2][4], al[2][4];
            const int acol = (k0g + (L >> 4) * 8) * 2;
            #pragma unroll
            for (int mt = 0; mt < 2; ++mt) {
                const int arow = 32 * wm + 16 * mt + (L & 15);
                ldm_x4(ah[mt], Ah + arow * A_PITCH + acol);
                ldm_x4(al[mt], Al + arow * A_PITCH + acol);
            }
            #pragma unroll
            for (int ntp = 0; ntp < 4; ++ntp) {
                uint32_t bh4[4], bl4[4];
                const int nt_sel = 2 * ntp + (L >> 4);
                const int khalf  = (L >> 3) & 1;
                const int brow   = 64 * wn + 8 * nt_sel + (L & 7);
                const unsigned boff = (unsigned)brow * 32u
                                    + ((unsigned)(khalf * 16) ^ (unsigned)(((brow >> 2) & 1) * 16));
                ldm_x4(bh4, Bbuf + boff);
                ldm_x4(bl4, Bbuf + B_PLANE + boff);
                #pragma unroll
                for (int mt = 0; mt < 2; ++mt) {
                    mma16816(acc[mt][2 * ntp],     ah[mt], bh4);
                    mma16816(acc[mt][2 * ntp],     al[mt], bh4);
                    mma16816(acc[mt][2 * ntp],     ah[mt], bl4);
                    mma16816(acc[mt][2 * ntp + 1], ah[mt], bh4 + 2);
                    mma16816(acc[mt][2 * ntp + 1], al[mt], bh4 + 2);
                    mma16816(acc[mt][2 * ntp + 1], ah[mt], bl4 + 2);
                }
            }
        }

        if ((p & 15) == 15) {
            __syncthreads();   // all compute done; film visible
            if (l < 3) {
                // FiLM + sin -> A planes; zero acc
                #pragma unroll
                for (int mt = 0; mt < 2; ++mt) {
                    const int r0 = 32 * wm + 16 * mt + (L >> 2);
                    #pragma unroll
                    for (int nt = 0; nt < 8; ++nt) {
                        const int n0 = 64 * wn + 8 * nt + 2 * (L & 3);
                        const float g0 = 1.0f + film[n0], g1 = 1.0f + film[n0 + 1];
                        const float e0 = film[256 + n0],  e1 = film[256 + n0 + 1];
                        const float h0 = film[512 + n0],  h1 = film[512 + n0 + 1];
                        float* a = acc[mt][nt];
                        float x00 = __sinf(30.0f * fmaf(a[0] + h0, g0, e0));
                        float x01 = __sinf(30.0f * fmaf(a[1] + h1, g1, e1));
                        float x10 = __sinf(30.0f * fmaf(a[2] + h0, g0, e0));
                        float x11 = __sinf(30.0f * fmaf(a[3] + h1, g1, e1));
                        uint32_t lo0, hi0 = pack_split(x00, x01, lo0);
                        uint32_t lo1, hi1 = pack_split(x10, x11, lo1);
                        *reinterpret_cast<uint32_t*>(Ah + r0 * A_PITCH + n0 * 2)       = hi0;
                        *reinterpret_cast<uint32_t*>(Al + r0 * A_PITCH + n0 * 2)       = lo0;
                        *reinterpret_cast<uint32_t*>(Ah + (r0 + 8) * A_PITCH + n0 * 2) = hi1;
                        *reinterpret_cast<uint32_t*>(Al + (r0 + 8) * A_PITCH + n0 * 2) = lo1;
                        a[0] = 0.f; a[1] = 0.f; a[2] = 0.f; a[3] = 0.f;
                    }
                }
            } else {
                // final layer: FiLM + sin -> output head partials
                float pacc[4][3];
                #pragma unroll
                for (int i = 0; i < 4; ++i)
                    #pragma unroll
                    for (int c = 0; c < 3; ++c) pacc[i][c] = 0.f;
                #pragma unroll
                for (int mt = 0; mt < 2; ++mt) {
                    #pragma unroll
                    for (int nt = 0; nt < 8; ++nt) {
                        const int n0 = 64 * wn + 8 * nt + 2 * (L & 3);
                        const float g0 = 1.0f + film[n0], g1 = 1.0f + film[n0 + 1];
                        const float e0 = film[256 + n0],  e1 = film[256 + n0 + 1];
                        const float h0 = film[512 + n0],  h1 = film[512 + n0 + 1];
                        float* a = acc[mt][nt];
                        float x00 = __sinf(30.0f * fmaf(a[0] + h0, g0, e0));
                        float x01 = __sinf(30.0f * fmaf(a[1] + h1, g1, e1));
                        float x10 = __sinf(30.0f * fmaf(a[2] + h0, g0, e0));
                        float x11 = __sinf(30.0f * fmaf(a[3] + h1, g1, e1));
                        #pragma unroll
                        for (int c = 0; c < 3; ++c) {
                            const float wl0 = Wlg[n0 * 3 + c];
                            const float wl1 = Wlg[(n0 + 1) * 3 + c];
                            pacc[mt * 2][c]     = fmaf(x00, wl0, fmaf(x01, wl1, pacc[mt * 2][c]));
                            pacc[mt * 2 + 1][c] = fmaf(x10, wl0, fmaf(x11, wl1, pacc[mt * 2 + 1][c]));
                        }
                    }
                }
                #pragma unroll
                for (int i = 0; i < 4; ++i)
                    #pragma unroll
                    for (int c = 0; c < 3; ++c) {
                        pacc[i][c] += __shfl_xor_sync(~0u, pacc[i][c], 1);
                        pacc[i][c] += __shfl_xor_sync(~0u, pacc[i][c], 2);
                    }
                if ((L & 3) == 0) {
                    #pragma unroll
                    for (int mt = 0; mt < 2; ++mt) {
                        const int r0 = 32 * wm + 16 * mt + (L >> 2);
                        #pragma unroll
                        for (int c = 0; c < 3; ++c) {
                            red[r0 * 12 + wn * 3 + c]       = pacc[mt * 2][c];
                            red[(r0 + 8) * 12 + wn * 3 + c] = pacc[mt * 2 + 1][c];
                        }
                    }
                }
            }
        }
    }

    __syncthreads();
    if (t < 64) {
        float* op = out + ((size_t)(b * 4096 + m_base + t)) * 3;
        #pragma unroll
        for (int c = 0; c < 3; ++c)
            op[c] = (red[t * 12 + c] + red[t * 12 + 3 + c])
                  + (red[t * 12 + 6 + c] + red[t * 12 + 9 + c]) + blg[c];
    }
}

// =================================================================
extern "C" void kernel_launch(void* const* d_in, const int* in_sizes, int n_in,
                              void* d_out, int out_size) {
    const float* coords  = (const float*)d_in[0];
    const int*   lidx    = (const int*)  d_in[1];
    const float* latents = (const float*)d_in[2];
    const float* emb     = (const float*)d_in[3];
    const float* mod_W   = (const float*)d_in[4];
    const float* mod_b   = (const float*)d_in[5];
    const float* W0      = (const float*)d_in[6];
    const float* b0      = (const float*)d_in[7];
    const float* Wh      = (const float*)d_in[8];
    const float* bh      = (const float*)d_in[9];
    const float* Wl      = (const float*)d_in[10];
    const float* bl      = (const float*)d_in[11];
    float* out = (float*)d_out;

    prep_kernel<<<512, 256>>>(Wh);
    vq_kernel<<<16, 1024>>>(lidx, latents, emb, mod_W, mod_b);
    loss_kernel<<<1, 32>>>(out, out_size);

    const int smem = 109568;
    cudaFuncSetAttribute(dec_mma, cudaFuncAttributeMaxDynamicSharedMemorySize, smem);
    dec_mma<<<dim3(64, 16), 256, smem>>>(coords, W0, b0, bh, Wl, bl, out);
}

// round 11
// speedup vs baseline: 1.8909x; 1.0138x over previous
#include <cuda_runtime.h>
#include <cuda_bf16.h>
#include <cstdint>

typedef unsigned long long ull;

// ---------------- scratch (no allocation allowed) ----------------
__device__ float g_mods[16 * 5 * 512];         // [b][layer][gam|bet]
__device__ float g_loss[16];                   // per-b summed loss
// transposed + bf16 hi/lo split weights:
// [layer][plane hi/lo][n=256][k=256] bf16  -> 4 * 2 * 131072 bytes
__device__ unsigned char g_B[4 * 2 * 131072];

// ---------------- helpers ----------------
__device__ __forceinline__ uint32_t smem_u32(const void* p) {
    uint32_t a;
    asm("{ .reg .u64 t; cvta.to.shared.u64 t, %1; cvt.u32.u64 %0, t; }"
        : "=r"(a) : "l"(p));
    return a;
}
__device__ __forceinline__ void cp16s(uint32_t dst, const void* src) {
    asm volatile("cp.async.ca.shared.global [%0], [%1], 16;" :: "r"(dst), "l"(src));
}
__device__ __forceinline__ void ldm4s(uint32_t* r, uint32_t a) {
    asm volatile("ldmatrix.sync.aligned.m8n8.x4.shared.b16 {%0,%1,%2,%3}, [%4];"
                 : "=r"(r[0]), "=r"(r[1]), "=r"(r[2]), "=r"(r[3]) : "r"(a));
}
__device__ __forceinline__ void mma16816(float* c, const uint32_t* a, const uint32_t* b) {
    asm volatile(
        "mma.sync.aligned.m16n8k16.row.col.f32.bf16.bf16.f32 "
        "{%0,%1,%2,%3}, {%4,%5,%6,%7}, {%8,%9}, {%0,%1,%2,%3};"
        : "+f"(c[0]), "+f"(c[1]), "+f"(c[2]), "+f"(c[3])
        : "r"(a[0]), "r"(a[1]), "r"(a[2]), "r"(a[3]), "r"(b[0]), "r"(b[1]));
}
__device__ __forceinline__ uint32_t pack_split(float x0, float x1, uint32_t& lo_out) {
    __nv_bfloat16 h0 = __float2bfloat16(x0);
    __nv_bfloat16 h1 = __float2bfloat16(x1);
    __nv_bfloat16 l0 = __float2bfloat16(x0 - __bfloat162float(h0));
    __nv_bfloat16 l1 = __float2bfloat16(x1 - __bfloat162float(h1));
    lo_out = ((uint32_t)__bfloat16_as_ushort(l1) << 16) | __bfloat16_as_ushort(l0);
    return ((uint32_t)__bfloat16_as_ushort(h1) << 16) | __bfloat16_as_ushort(h0);
}

// =================================================================
// Kernel 1: fused weight-prep (blocks 0..127) + residual VQ + FiLM
// mods (blocks 128..143). 1024 threads.
// =================================================================
__global__ __launch_bounds__(1024)
void prep_vq_kernel(const int* __restrict__ lidx,
                    const float* __restrict__ latents,
                    const float* __restrict__ emb,
                    const float* __restrict__ mod_W,
                    const float* __restrict__ mod_b,
                    const float* __restrict__ Whg) {
    if (blockIdx.x < 128) {
        // ---- weight prep: Wt[n][k] bf16 hi/lo planes ----
        const int i = blockIdx.x * 1024 + threadIdx.x;   // 131072 total
        const int layer = i >> 15;
        const int kp    = (i >> 8) & 127;
        const int n     = i & 255;
        const int k     = kp * 2;
        float w0 = Whg[(size_t)layer * 65536 + (size_t)k * 256 + n];
        float w1 = Whg[(size_t)layer * 65536 + (size_t)(k + 1) * 256 + n];
        uint32_t lo, hi = pack_split(w0, w1, lo);
        unsigned char* base = g_B + (size_t)layer * 262144;
        *reinterpret_cast<uint32_t*>(base + n * 512 + k * 2)          = hi;
        *reinterpret_cast<uint32_t*>(base + 131072 + n * 512 + k * 2) = lo;
        return;
    }

    // ---- residual VQ for b = blockIdx.x - 128 ----
    __shared__ float r[256];
    __shared__ float q[256];
    __shared__ float wsc[32];
    __shared__ int   wci[32];
    __shared__ float s_d, s_r2;
    __shared__ int   s_c;

    const int b = blockIdx.x - 128, t = threadIdx.x;
    const int lane = t & 31, wid = t >> 5;

    if (t < 256) {
        const float* lp = latents + (size_t)lidx[b] * 1024;
        float z = lp[t] + lp[256 + t] + lp[512 + t] + lp[768 + t];
        r[t] = z; q[t] = 0.f;
    }
    __syncthreads();

    if (wid == 0) {
        float rz = 0.f;
        #pragma unroll
        for (int j = 0; j < 8; ++j) { float v = r[lane * 8 + j]; rz = fmaf(v, v, rz); }
        #pragma unroll
        for (int o = 16; o; o >>= 1) rz += __shfl_xor_sync(~0u, rz, o);
        if (lane == 0) s_r2 = rz;
    }
    float loss = 0.f;
    __syncthreads();

    for (int s = 0; s < 4; ++s) {
        float4 rj0 = reinterpret_cast<const float4*>(r)[lane * 2];
        float4 rj1 = reinterpret_cast<const float4*>(r)[lane * 2 + 1];
        float best = -3.4e38f;
        int   bi   = 0;
        const int c0 = wid * 32;
        #pragma unroll 8
        for (int i = 0; i < 32; ++i) {
            const int c = c0 + i;
            const float4* E4 = reinterpret_cast<const float4*>(emb)
                               + (size_t)(s * 1024 + c) * 64 + lane * 2;
            float4 e0 = E4[0], e1 = E4[1];
            float p = e0.x * rj0.x + e0.y * rj0.y + e0.z * rj0.z + e0.w * rj0.w
                    + e1.x * rj1.x + e1.y * rj1.y + e1.z * rj1.z + e1.w * rj1.w;
            #pragma unroll
            for (int o = 16; o; o >>= 1) p += __shfl_xor_sync(~0u, p, o);
            if (p > best) { best = p; bi = c; }
        }
        if (lane == 0) { wsc[wid] = best; wci[wid] = bi; }
        __syncthreads();
        if (wid == 0) {
            float v = wsc[lane]; int ci = wci[lane];
            #pragma unroll
            for (int o = 16; o; o >>= 1) {
                float ov = __shfl_down_sync(~0u, v,  o);
                int   oi = __shfl_down_sync(~0u, ci, o);
                if (ov > v || (ov == v && oi < ci)) { v = ov; ci = oi; }
            }
            if (lane == 0) { s_c = ci; s_d = 1.0f - 2.0f * v; }
        }
        __syncthreads();
        if (t == 0) { loss += s_d + s_r2; s_r2 += s_d; }
        const int cmin = s_c;
        if (t < 256) {
            float e = emb[((size_t)s * 1024 + cmin) * 256 + t];
            q[t] += e; r[t] -= e;
        }
        __syncthreads();
    }
    if (t == 0) g_loss[b] = loss;

    // ---- fused FiLM mods for this b ----
    for (int i = t; i < 2560; i += 1024) {
        const int l = i >> 9, h = i & 511;
        float a = mod_b[l * 512 + h];
        const float* Wp = mod_W + (size_t)l * 131072 + h;
        #pragma unroll 16
        for (int d = 0; d < 256; ++d)
            a = fmaf(q[d], Wp[(size_t)d * 512], a);
        g_mods[b * 2560 + i] = a;
    }
}

// =================================================================
// Kernel 2: HMMA SIREN decoder (+ vq_loss finalize in block (0,0)).
// grid (64 tiles, 16 b), 256 thr, M_TILE=64, 2 CTAs/SM (128 regs).
// A planes: [64m][256k] bf16 hi/lo, pitch 528B.
// B: 16-k chunks [256n][16k] hi/lo, XOR-swizzled 32B pitch,
//    double-buffered cp.async. All ldm/cp addresses hoisted.
// Warps 2m x 4n; warp tile 32m x 64n; 3-term Ah*Bh + Al*Bh + Ah*Bl.
// =================================================================
#define A_PITCH 528
#define A_PLANE 33792
#define B_PLANE 8192
#define B_BUF   16384

__global__ __launch_bounds__(256, 2)
void dec_mma(const float* __restrict__ coords,
             const float* __restrict__ W0g,
             const float* __restrict__ b0g,
             const float* __restrict__ bhg,
             const float* __restrict__ Wlg,
             const float* __restrict__ blg,
             float* __restrict__ out, int out_size) {
    extern __shared__ char smc[];
    char*  Ah   = smc;                         // 33792
    char*  Al   = smc + A_PLANE;               // 33792
    char*  Bb   = smc + 2 * A_PLANE;           // 32768 (2 bufs x 2 planes)
    float* w0s  = (float*)(smc + 100352);      // 768 f
    float* film = (float*)(smc + 103424);      // 768 f (gam|bet|bh, one layer)
    float* red  = (float*)(smc + 106496);      // 64*12 f
    // total 109568 B

    const int b      = blockIdx.y;
    const int m_base = blockIdx.x * 64;
    const int t  = threadIdx.x;
    const int L  = t & 31;
    const int wid = t >> 5;
    const int wm = wid >> 2;       // 0..1 (m)
    const int wn = wid & 3;        // 0..3 (n)

    // ---- hoisted addresses (all p-invariant) ----
    const uint32_t AhS = smem_u32(Ah), AlS = smem_u32(Al), BbS = smem_u32(Bb);
    uint32_t aBaseH[2], aBaseL[2];
    #pragma unroll
    for (int mt = 0; mt < 2; ++mt) {
        const int arow = 32 * wm + 16 * mt + (L & 15);
        aBaseH[mt] = AhS + arow * A_PITCH;
        aBaseL[mt] = AlS + arow * A_PITCH;
    }
    uint32_t bOffH[4], bOffL[4];
    {
        const int khalf = (L >> 3) & 1;
        #pragma unroll
        for (int ntp = 0; ntp < 4; ++ntp) {
            const int nt_sel = 2 * ntp + (L >> 4);
            const int brow   = 64 * wn + 8 * nt_sel + (L & 7);
            const uint32_t boff = (uint32_t)brow * 32u
                                + ((uint32_t)(khalf * 16) ^ (uint32_t)(((brow >> 2) & 1) * 16));
            bOffH[ntp] = BbS + boff;
            bOffL[ntp] = BbS + B_PLANE + boff;
        }
    }
    uint32_t cpDst[4], cpSrc[4];
    #pragma unroll
    for (int j = 0; j < 4; ++j) {
        const int c = t + j * 256;
        const int plane = c >> 9;
        const int cc = c & 511;
        const int rr = cc >> 1, h = cc & 1;
        cpDst[j] = BbS + plane * B_PLANE + rr * 32 + ((h * 16) ^ (((rr >> 2) & 1) * 16));
        cpSrc[j] = (uint32_t)(plane * 131072 + rr * 512 + h * 16);
    }

    // stage W0/b0
    for (int i = t; i < 768; i += 256) w0s[i] = (i < 512) ? W0g[i] : b0g[i - 512];

    // prefetch B chunk 0 (layer 0, k0) into buf 0
    {
        #pragma unroll
        for (int j = 0; j < 4; ++j) cp16s(cpDst[j], g_B + cpSrc[j]);
        asm volatile("cp.async.commit_group;");
    }
    __syncthreads();

    // ---- layer 0: fill A planes (row m = t&63, quarter q = t>>6) ----
    {
        const int m = t & 63, qd = t >> 6;
        const float2 c2 = reinterpret_cast<const float2*>(coords)[b * 4096 + m_base + m];
        char* rowH = Ah + m * A_PITCH;
        char* rowL = Al + m * A_PITCH;
        #pragma unroll 4
        for (int n = qd * 64; n < qd * 64 + 64; n += 2) {
            float p0 = fmaf(c2.x, w0s[n],     fmaf(c2.y, w0s[256 + n],     w0s[512 + n]));
            float p1 = fmaf(c2.x, w0s[n + 1], fmaf(c2.y, w0s[256 + n + 1], w0s[512 + n + 1]));
            float x0 = __sinf(30.0f * p0);
            float x1 = __sinf(30.0f * p1);
            uint32_t lo, hi = pack_split(x0, x1, lo);
            *reinterpret_cast<uint32_t*>(rowH + n * 2) = hi;
            *reinterpret_cast<uint32_t*>(rowL + n * 2) = lo;
        }
    }

    float acc[2][8][4];
    #pragma unroll
    for (int mt = 0; mt < 2; ++mt)
        #pragma unroll
        for (int nt = 0; nt < 8; ++nt)
            #pragma unroll
            for (int j = 0; j < 4; ++j) acc[mt][nt][j] = 0.f;

    // 64 iterations: 4 layers x 16 chunks of 16 k
    for (int p = 0; p < 64; ++p) {
        __syncthreads();   // prev compute done; epilogue A writes visible

        if (p < 63) {      // prefetch chunk p+1
            const unsigned char* sb = g_B + (size_t)(((p + 1) >> 4) * 262144 + ((p + 1) & 15) * 32);
            const uint32_t db = ((p + 1) & 1) * B_BUF;
            #pragma unroll
            for (int j = 0; j < 4; ++j) cp16s(cpDst[j] + db, sb + cpSrc[j]);
            asm volatile("cp.async.commit_group;");
            asm volatile("cp.async.wait_group 1;");
        } else {
            asm volatile("cp.async.wait_group 0;");
        }
        __syncthreads();   // chunk p visible

        const int l = p >> 4;

        if ((p & 15) == 15) {   // preload film for this layer (read after next sync)
            for (int i = t; i < 768; i += 256)
                film[i] = (i < 512) ? g_mods[b * 2560 + 512 + l * 512 + i]
                                    : bhg[l * 256 + (i - 512)];
        }

        {
            uint32_t ah[2][4], al[2][4];
            const uint32_t acol = (uint32_t)(((p & 15) << 5) + ((L >> 4) << 4));
            ldm4s(ah[0], aBaseH[0] + acol);
            ldm4s(ah[1], aBaseH[1] + acol);
            ldm4s(al[0], aBaseL[0] + acol);
            ldm4s(al[1], aBaseL[1] + acol);
            const uint32_t bsel = (p & 1) * B_BUF;
            #pragma unroll
            for (int ntp = 0; ntp < 4; ++ntp) {
                uint32_t bh4[4], bl4[4];
                ldm4s(bh4, bOffH[ntp] + bsel);
                ldm4s(bl4, bOffL[ntp] + bsel);
                #pragma unroll
                for (int mt = 0; mt < 2; ++mt) {
                    mma16816(acc[mt][2 * ntp],     ah[mt], bh4);
                    mma16816(acc[mt][2 * ntp],     al[mt], bh4);
                    mma16816(acc[mt][2 * ntp],     ah[mt], bl4);
                    mma16816(acc[mt][2 * ntp + 1], ah[mt], bh4 + 2);
                    mma16816(acc[mt][2 * ntp + 1], al[mt], bh4 + 2);
                    mma16816(acc[mt][2 * ntp + 1], ah[mt], bl4 + 2);
                }
            }
        }

        if ((p & 15) == 15) {
            __syncthreads();   // all compute done; film visible
            if (l < 3) {
                // FiLM + sin -> A planes; zero acc
                #pragma unroll
                for (int mt = 0; mt < 2; ++mt) {
                    const int r0 = 32 * wm + 16 * mt + (L >> 2);
                    #pragma unroll
                    for (int nt = 0; nt < 8; ++nt) {
                        const int n0 = 64 * wn + 8 * nt + 2 * (L & 3);
                        const float g0 = 1.0f + film[n0], g1 = 1.0f + film[n0 + 1];
                        const float e0 = film[256 + n0],  e1 = film[256 + n0 + 1];
                        const float h0 = film[512 + n0],  h1 = film[512 + n0 + 1];
                        float* a = acc[mt][nt];
                        float x00 = __sinf(30.0f * fmaf(a[0] + h0, g0, e0));
                        float x01 = __sinf(30.0f * fmaf(a[1] + h1, g1, e1));
                        float x10 = __sinf(30.0f * fmaf(a[2] + h0, g0, e0));
                        float x11 = __sinf(30.0f * fmaf(a[3] + h1, g1, e1));
                        uint32_t lo0, hi0 = pack_split(x00, x01, lo0);
                        uint32_t lo1, hi1 = pack_split(x10, x11, lo1);
                        *reinterpret_cast<uint32_t*>(Ah + r0 * A_PITCH + n0 * 2)       = hi0;
                        *reinterpret_cast<uint32_t*>(Al + r0 * A_PITCH + n0 * 2)       = lo0;
                        *reinterpret_cast<uint32_t*>(Ah + (r0 + 8) * A_PITCH + n0 * 2) = hi1;
                        *reinterpret_cast<uint32_t*>(Al + (r0 + 8) * A_PITCH + n0 * 2) = lo1;
                        a[0] = 0.f; a[1] = 0.f; a[2] = 0.f; a[3] = 0.f;
                    }
                }
            } else {
                // final layer: FiLM + sin -> output head partials
                float pacc[4][3];
                #pragma unroll
                for (int i = 0; i < 4; ++i)
                    #pragma unroll
                    for (int c = 0; c < 3; ++c) pacc[i][c] = 0.f;
                #pragma unroll
                for (int mt = 0; mt < 2; ++mt) {
                    #pragma unroll
                    for (int nt = 0; nt < 8; ++nt) {
                        const int n0 = 64 * wn + 8 * nt + 2 * (L & 3);
                        const float g0 = 1.0f + film[n0], g1 = 1.0f + film[n0 + 1];
                        const float e0 = film[256 + n0],  e1 = film[256 + n0 + 1];
                        const float h0 = film[512 + n0],  h1 = film[512 + n0 + 1];
                        float* a = acc[mt][nt];
                        float x00 = __sinf(30.0f * fmaf(a[0] + h0, g0, e0));
                        float x01 = __sinf(30.0f * fmaf(a[1] + h1, g1, e1));
                        float x10 = __sinf(30.0f * fmaf(a[2] + h0, g0, e0));
                        float x11 = __sinf(30.0f * fmaf(a[3] + h1, g1, e1));
                        #pragma unroll
                        for (int c = 0; c < 3; ++c) {
                            const float wl0 = Wlg[n0 * 3 + c];
                            const float wl1 = Wlg[(n0 + 1) * 3 + c];
                            pacc[mt * 2][c]     = fmaf(x00, wl0, fmaf(x01, wl1, pacc[mt * 2][c]));
                            pacc[mt * 2 + 1][c] = fmaf(x10, wl0, fmaf(x11, wl1, pacc[mt * 2 + 1][c]));
                        }
                    }
                }
                #pragma unroll
                for (int i = 0; i < 4; ++i)
                    #pragma unroll
                    for (int c = 0; c < 3; ++c) {
                        pacc[i][c] += __shfl_xor_sync(~0u, pacc[i][c], 1);
                        pacc[i][c] += __shfl_xor_sync(~0u, pacc[i][c], 2);
                    }
                if ((L & 3) == 0) {
                    #pragma unroll
                    for (int mt = 0; mt < 2; ++mt) {
                        const int r0 = 32 * wm + 16 * mt + (L >> 2);
                        #pragma unroll
                        for (int c = 0; c < 3; ++c) {
                            red[r0 * 12 + wn * 3 + c]       = pacc[mt * 2][c];
                            red[(r0 + 8) * 12 + wn * 3 + c] = pacc[mt * 2 + 1][c];
                        }
                    }
                }
            }
        }
    }

    __syncthreads();
    if (t < 64) {
        float* op = out + ((size_t)(b * 4096 + m_base + t)) * 3;
        #pragma unroll
        for (int c = 0; c < 3; ++c)
            op[c] = (red[t * 12 + c] + red[t * 12 + 3 + c])
                  + (red[t * 12 + 6 + c] + red[t * 12 + 9 + c]) + blg[c];
    }

    // vq_loss finalize (g_loss ready: prep_vq completed before this kernel)
    if (blockIdx.x == 0 && blockIdx.y == 0 && t == 0) {
        float s = 0.f;
        #pragma unroll
        for (int i = 0; i < 16; ++i) s += g_loss[i];
        out[out_size - 1] = s * (1.0f / 65536.0f);
    }
}

// =================================================================
extern "C" void kernel_launch(void* const* d_in, const int* in_sizes, int n_in,
                              void* d_out, int out_size) {
    const float* coords  = (const float*)d_in[0];
    const int*   lidx    = (const int*)  d_in[1];
    const float* latents = (const float*)d_in[2];
    const float* emb     = (const float*)d_in[3];
    const float* mod_W   = (const float*)d_in[4];
    const float* mod_b   = (const float*)d_in[5];
    const float* W0      = (const float*)d_in[6];
    const float* b0      = (const float*)d_in[7];
    const float* Wh      = (const float*)d_in[8];
    const float* bh      = (const float*)d_in[9];
    const float* Wl      = (const float*)d_in[10];
    const float* bl      = (const float*)d_in[11];
    float* out = (float*)d_out;

    prep_vq_kernel<<<144, 1024>>>(lidx, latents, emb, mod_W, mod_b, Wh);

    const int smem = 109568;
    cudaFuncSetAttribute(dec_mma, cudaFuncAttributeMaxDynamicSharedMemorySize, smem);
    dec_mma<<<dim3(64, 16), 256, smem>>>(coords, W0, b0, bh, Wl, bl, out, out_size);
}